// round 14
// baseline (speedup 1.0000x reference)
#include <cuda_runtime.h>
#include <cuda_bf16.h>

#define B_  16
#define S_  128
#define T_  128
#define ST_ 127
#define E_  256
#define H_  512
#define H2_ 1024
#define H3_ 1536
#define KD_ 1280
#define KO_ 1792
#define V_  32000
#define MPAD_ 2048
#define K3_ (3*KO_)
#define HP_ 516
#define NCH_ 168
#define STG_A 20480
#define STG_B 10240
#define STG_SZ 30720
#define TSPLIT_ 64

typedef unsigned int u32;
typedef unsigned long long u64;

__device__ float g_emb    [B_*S_*E_];
__device__ float g_emb_rev[B_*S_*E_];
__device__ float g_emb_in [ST_*B_*E_];
__device__ float g_GI_f   [B_*S_*H3_];
__device__ float g_GI_b   [B_*S_*H3_];
__device__ float g_GIe    [ST_*B_*H3_];
__device__ float g_enc_out[B_*S_*H2_];
__device__ float g_out_bR [B_*S_*H_];
__device__ float g_encP   [B_*S_*H_];
__device__ float g_encW   [B_*S_*H3_];
__device__ float g_feat   [ST_*B_*KO_];
__device__ float g_hf  [2*B_*H_];
__device__ float g_hb  [2*B_*H_];
__device__ float g_hdec[2*B_*H_];
__device__ float g_dps [B_*H_];
__device__ float g_gict[B_*H3_];
__device__ __align__(16) unsigned char g_A3p[(size_t)8*NCH_*STG_A];
__device__ __align__(16) unsigned char g_B3p[(size_t)250*NCH_*STG_B];

struct GBS { unsigned cnt; unsigned p0[31]; unsigned gen; unsigned p1[31]; };
__device__ GBS g_gb[3];

__device__ __forceinline__ void gbar2(unsigned* cnt, unsigned* gen, unsigned era, unsigned nb) {
    __syncthreads();
    if (threadIdx.x == 0) {
        unsigned prev;
        asm volatile("atom.add.acq_rel.gpu.global.u32 %0, [%1], 1;"
                     : "=r"(prev) : "l"(cnt) : "memory");
        if (prev == era*nb - 1u) {
            asm volatile("st.release.gpu.global.u32 [%0], %1;" :: "l"(gen), "r"(era) : "memory");
        } else {
            unsigned g;
            do {
                asm volatile("ld.acquire.gpu.global.u32 %0, [%1];" : "=r"(g) : "l"(gen) : "memory");
            } while (g < era);
        }
    }
    __syncthreads();
}

__device__ __forceinline__ float sigf(float x) { return 1.f / (1.f + expf(-x)); }
__device__ __forceinline__ float tanhap(float x) {
    float y; asm("tanh.approx.f32 %0, %1;" : "=f"(y) : "f"(x)); return y;
}
__device__ __forceinline__ u64 f2pack(float a, float b) {
    u64 r; asm("mov.b64 %0, {%1, %2};" : "=l"(r) : "r"(__float_as_uint(a)), "r"(__float_as_uint(b)));
    return r;
}
__device__ __forceinline__ void f2fma(u64& d, u64 a, u64 b) {
    asm("fma.rn.f32x2 %0, %1, %2, %0;" : "+l"(d) : "l"(a), "l"(b));
}
__device__ __forceinline__ float2 f2unpack(u64 v) {
    unsigned lo, hi; asm("mov.b64 {%0, %1}, %2;" : "=r"(lo), "=r"(hi) : "l"(v));
    return make_float2(__uint_as_float(lo), __uint_as_float(hi));
}
__device__ __forceinline__ void dot3_512(const float* __restrict__ x,
    const float* __restrict__ r0, const float* __restrict__ r1,
    const float* __restrict__ r2, float& o0, float& o1, float& o2)
{
    u64 a0=0,a1=0,b0=0,b1=0,c0=0,c1=0;
    #pragma unroll 8
    for (int k = 0; k < H_; k += 4) {
        float4 xv = *(const float4*)(x + k);
        u64 xlo = f2pack(xv.x, xv.y), xhi = f2pack(xv.z, xv.w);
        float4 w0 = *(const float4*)(r0 + k);
        f2fma(a0, xlo, f2pack(w0.x, w0.y)); f2fma(a1, xhi, f2pack(w0.z, w0.w));
        float4 w1 = *(const float4*)(r1 + k);
        f2fma(b0, xlo, f2pack(w1.x, w1.y)); f2fma(b1, xhi, f2pack(w1.z, w1.w));
        float4 w2 = *(const float4*)(r2 + k);
        f2fma(c0, xlo, f2pack(w2.x, w2.y)); f2fma(c1, xhi, f2pack(w2.z, w2.w));
    }
    float2 p, q;
    p = f2unpack(a0); q = f2unpack(a1); o0 = (p.x + q.x) + (p.y + q.y);
    p = f2unpack(b0); q = f2unpack(b1); o1 = (p.x + q.x) + (p.y + q.y);
    p = f2unpack(c0); q = f2unpack(c1); o2 = (p.x + q.x) + (p.y + q.y);
}
__device__ __forceinline__ void dot3_128(const float* __restrict__ x,
    const float* __restrict__ r0, const float* __restrict__ r1,
    const float* __restrict__ r2, float& o0, float& o1, float& o2)
{
    u64 a0=0,a1=0,b0=0,b1=0,c0=0,c1=0;
    #pragma unroll
    for (int k = 0; k < 128; k += 4) {
        float4 xv = *(const float4*)(x + k);
        u64 xlo = f2pack(xv.x, xv.y), xhi = f2pack(xv.z, xv.w);
        float4 w0 = *(const float4*)(r0 + k);
        f2fma(a0, xlo, f2pack(w0.x, w0.y)); f2fma(a1, xhi, f2pack(w0.z, w0.w));
        float4 w1 = *(const float4*)(r1 + k);
        f2fma(b0, xlo, f2pack(w1.x, w1.y)); f2fma(b1, xhi, f2pack(w1.z, w1.w));
        float4 w2 = *(const float4*)(r2 + k);
        f2fma(c0, xlo, f2pack(w2.x, w2.y)); f2fma(c1, xhi, f2pack(w2.z, w2.w));
    }
    float2 p, q;
    p = f2unpack(a0); q = f2unpack(a1); o0 = (p.x + q.x) + (p.y + q.y);
    p = f2unpack(b0); q = f2unpack(b1); o1 = (p.x + q.x) + (p.y + q.y);
    p = f2unpack(c0); q = f2unpack(c1); o2 = (p.x + q.x) + (p.y + q.y);
}

__device__ __forceinline__ u32 s2u(const void* p) {
    u32 a; asm("{ .reg .u64 t; cvta.to.shared.u64 t, %1; cvt.u32.u64 %0, t; }" : "=r"(a) : "l"(p));
    return a;
}
__device__ __forceinline__ void ldmA4(u32 addr, u32* a) {
    asm volatile("ldmatrix.sync.aligned.m8n8.x4.shared.b16 {%0,%1,%2,%3}, [%4];"
        : "=r"(a[0]), "=r"(a[1]), "=r"(a[2]), "=r"(a[3]) : "r"(addr));
}
__device__ __forceinline__ void ldmB2(u32 addr, u32* b) {
    asm volatile("ldmatrix.sync.aligned.m8n8.x2.shared.b16 {%0,%1}, [%2];"
        : "=r"(b[0]), "=r"(b[1]) : "r"(addr));
}
__device__ __forceinline__ void mma16816(float* c, const u32* a, const u32* b) {
    asm volatile("mma.sync.aligned.m16n8k16.row.col.f32.bf16.bf16.f32 "
        "{%0,%1,%2,%3}, {%4,%5,%6,%7}, {%8,%9}, {%0,%1,%2,%3};"
        : "+f"(c[0]), "+f"(c[1]), "+f"(c[2]), "+f"(c[3])
        : "r"(a[0]), "r"(a[1]), "r"(a[2]), "r"(a[3]), "r"(b[0]), "r"(b[1]));
}

#define MB_INIT(mb, c)   asm volatile("mbarrier.init.shared.b64 [%0], %1;" :: "r"((u32)(mb)), "r"((u32)(c)) : "memory")
#define MB_EXPECT_TX(mb, n) asm volatile("mbarrier.arrive.expect_tx.shared.b64 _, [%0], %1;" :: "r"((u32)(mb)), "r"((u32)(n)) : "memory")
#define BULK_G2S(dst, src, n, mb) \
    asm volatile("cp.async.bulk.shared::cluster.global.mbarrier::complete_tx::bytes [%0], [%1], %2, [%3];" \
        :: "r"((u32)(dst)), "l"(src), "r"((u32)(n)), "r"((u32)(mb)) : "memory")
#define MB_WAIT(mbar, par) do { \
    u32 _m = (u32)(mbar); u32 _p = (u32)(par); u32 _d; \
    asm volatile("{\n\t.reg .pred p;\n\t" \
        "mbarrier.try_wait.parity.acquire.cta.shared::cta.b64 p, [%1], %2;\n\t" \
        "selp.b32 %0, 1, 0, p;\n\t}" : "=r"(_d) : "r"(_m), "r"(_p) : "memory"); \
    if (!_d) { \
        asm volatile("{\n\t.reg .pred P1;\n\t" \
            "WL_%=:\n\t" \
            "mbarrier.try_wait.parity.acquire.cta.shared::cta.b64 P1, [%0], %1, 0x989680;\n\t" \
            "@P1 bra.uni WD_%=;\n\tbra.uni WL_%=;\n\tWD_%=:\n\t}" \
            :: "r"(_m), "r"(_p) : "memory"); \
    } } while (0)

// ---------------- gathers + init ----------------
__global__ void k_gather(const int* __restrict__ src, const int* __restrict__ len,
                         const int* __restrict__ tgt,
                         const float* __restrict__ enc_emb, const float* __restrict__ dec_emb)
{
    if (blockIdx.x == 0 && threadIdx.x == 0) {
        #pragma unroll
        for (int i = 0; i < 3; i++) { g_gb[i].cnt = 0u; g_gb[i].gen = 0u; }
        __threadfence();
    }
    const int total = B_*S_*E_;
    for (int i = blockIdx.x*blockDim.x + threadIdx.x; i < total; i += gridDim.x*blockDim.x) {
        int e = i % E_, s = (i / E_) % S_, b = i / (E_*S_);
        int L = len[b];
        g_emb[i] = enc_emb[(size_t)src[b*S_+s]*E_ + e];
        int r = (s < L) ? (L-1-s) : s;
        g_emb_rev[i] = enc_emb[(size_t)src[b*S_+r]*E_ + e];
        if (s < ST_) {
            float v = dec_emb[(size_t)tgt[b*T_+s]*E_ + e];
            size_t n = (size_t)s*B_ + b;
            g_emb_in[n*E_ + e] = v;
            g_feat[n*KO_ + (H_+H2_) + e] = v;
        }
        if (i < 2*B_*H_) { g_hf[i] = 0.f; g_hb[i] = 0.f; }
    }
}

// ---------------- packed bf16 hi/lo conversions ----------------
__device__ __forceinline__ u32 pack_bf2(float a0, float a1) {
    __nv_bfloat16 h0 = __float2bfloat16(a0), h1 = __float2bfloat16(a1);
    return (u32)__bfloat16_as_ushort(h0) | ((u32)__bfloat16_as_ushort(h1) << 16);
}
__device__ __forceinline__ u32 pack_bf2lo(float a0, float a1) {
    __nv_bfloat16 h0 = __float2bfloat16(a0), h1 = __float2bfloat16(a1);
    float l0 = a0 - __bfloat162float(h0), l1 = a1 - __bfloat162float(h1);
    return (u32)__bfloat16_as_ushort(__float2bfloat16(l0))
         | ((u32)__bfloat16_as_ushort(__float2bfloat16(l1)) << 16);
}
__global__ void k_convW(const float* __restrict__ W)
{
    const int NKG = KO_/8;
    const size_t total = (size_t)V_*NKG;
    for (size_t i = (size_t)blockIdx.x*blockDim.x + threadIdx.x; i < total;
         i += (size_t)gridDim.x*blockDim.x) {
        int n = (int)(i / NKG), k = (int)(i % NKG) * 8;
        const float* wp = W + (size_t)n*KO_ + k;
        float4 v0 = *(const float4*)(wp), v1 = *(const float4*)(wp + 4);
        uint4 hi, lo;
        hi.x = pack_bf2(v0.x, v0.y); hi.y = pack_bf2(v0.z, v0.w);
        hi.z = pack_bf2(v1.x, v1.y); hi.w = pack_bf2(v1.z, v1.w);
        lo.x = pack_bf2lo(v0.x, v0.y); lo.y = pack_bf2lo(v0.z, v0.w);
        lo.z = pack_bf2lo(v1.x, v1.y); lo.w = pack_bf2lo(v1.z, v1.w);
        int nb = n >> 7, r = n & 127;
        #pragma unroll
        for (int t3 = 0; t3 < 3; t3++) {
            int k3 = t3*KO_ + k;
            size_t off = (((size_t)nb*NCH_ + (k3 >> 5))*128 + r)*80 + (k3 & 31)*2;
            *(uint4*)(g_B3p + off) = (t3 == 1) ? lo : hi;
        }
    }
}
__global__ void k_convA(int mStart, int mEnd)
{
    const int NKG = KO_/8;
    const size_t lo_i = (size_t)mStart*NKG, hi_i = (size_t)mEnd*NKG;
    for (size_t i = lo_i + (size_t)blockIdx.x*blockDim.x + threadIdx.x; i < hi_i;
         i += (size_t)gridDim.x*blockDim.x) {
        int m = (int)(i / NKG), k = (int)(i % NKG) * 8;
        float4 v0 = make_float4(0.f,0.f,0.f,0.f), v1 = v0;
        if (m < ST_*B_) {
            const float* ap = g_feat + (size_t)m*KO_ + k;
            v0 = *(const float4*)(ap); v1 = *(const float4*)(ap + 4);
        }
        uint4 hi, lo;
        hi.x = pack_bf2(v0.x, v0.y); hi.y = pack_bf2(v0.z, v0.w);
        hi.z = pack_bf2(v1.x, v1.y); hi.w = pack_bf2(v1.z, v1.w);
        lo.x = pack_bf2lo(v0.x, v0.y); lo.y = pack_bf2lo(v0.z, v0.w);
        lo.z = pack_bf2lo(v1.x, v1.y); lo.w = pack_bf2lo(v1.z, v1.w);
        int mb = m >> 8, r = m & 255;
        #pragma unroll
        for (int t3 = 0; t3 < 3; t3++) {
            int k3 = t3*KO_ + k;
            size_t off = (((size_t)mb*NCH_ + (k3 >> 5))*256 + r)*80 + (k3 & 31)*2;
            *(uint4*)(g_A3p + off) = (t3 == 2) ? lo : hi;
        }
    }
}

// ---------------- HMMA output GEMM ----------------
__global__ __launch_bounds__(256, 1)
void k_outgemm(float* __restrict__ out, const float* __restrict__ bias, int bxOff)
{
    extern __shared__ __align__(16) char sm[];
    __shared__ __align__(8) u64 mbar[3];
    const int tid = threadIdx.x, wid = tid >> 5, lane = tid & 31;
    const int wm = wid >> 1, wn = wid & 1;
    const int bx = blockIdx.x + bxOff, by = blockIdx.y;
    const int m0 = bx * 256, n0 = by * 128;

    if (tid < 3) MB_INIT(s2u(&mbar[tid]), 1);
    __syncthreads();

    float acc[4][8][4];
    #pragma unroll
    for (int i = 0; i < 4; i++)
        #pragma unroll
        for (int j = 0; j < 8; j++)
            #pragma unroll
            for (int q = 0; q < 4; q++) acc[i][j][q] = 0.f;

    auto issue = [&](int c) {
        int slot = c % 3;
        u32 mb = s2u(&mbar[slot]);
        MB_EXPECT_TX(mb, STG_SZ);
        u32 da = s2u(sm + slot*STG_SZ);
        const unsigned char* ga = g_A3p + ((size_t)bx*NCH_ + c)*STG_A;
        const unsigned char* gb = g_B3p + ((size_t)by*NCH_ + c)*STG_B;
        BULK_G2S(da, ga, STG_A, mb);
        BULK_G2S(da + STG_A, gb, STG_B, mb);
    };
    if (tid == 0) { issue(0); issue(1); }

    const int NC = NCH_;
    for (int c = 0; c < NC; c++) {
        MB_WAIT(s2u(&mbar[c % 3]), (c/3) & 1);
        if (tid == 0 && c + 2 < NC) issue(c + 2);
        char* base = sm + (c % 3)*STG_SZ;
        const u32 aB = s2u(base), bB = s2u(base + STG_A);
        #pragma unroll
        for (int ks = 0; ks < 2; ks++) {
            u32 af[4][4], bf[8][2];
            #pragma unroll
            for (int fm = 0; fm < 4; fm++)
                ldmA4(aB + (u32)((wm*64 + fm*16 + (lane & 15))*80 + ks*32 + (lane >> 4)*16), af[fm]);
            #pragma unroll
            for (int fn = 0; fn < 8; fn++)
                ldmB2(bB + (u32)((wn*64 + fn*8 + (lane & 7))*80 + ks*32 + ((lane >> 3) & 1)*16), bf[fn]);
            #pragma unroll
            for (int fm = 0; fm < 4; fm++)
                #pragma unroll
                for (int fn = 0; fn < 8; fn++)
                    mma16816(acc[fm][fn], af[fm], bf[fn]);
        }
        __syncthreads();
    }

    #pragma unroll
    for (int fm = 0; fm < 4; fm++) {
        #pragma unroll
        for (int half = 0; half < 2; half++) {
            int m = m0 + wm*64 + fm*16 + (lane >> 2) + half*8;
            if (m >= ST_*B_) continue;
            float* orow = out + ((size_t)((m & 15)*ST_ + (m >> 4)))*V_;
            #pragma unroll
            for (int fn = 0; fn < 8; fn++) {
                int nc = n0 + wn*64 + fn*8 + (lane & 3)*2;
                float2 v;
                v.x = acc[fm][fn][half*2 + 0] + bias[nc];
                v.y = acc[fm][fn][half*2 + 1] + bias[nc + 1];
                *(float2*)(orow + nc) = v;
            }
        }
    }
}

// ---------------- SIMT f32 GEMM for the small matmuls ----------------
__global__ __launch_bounds__(256, 2)
void k_gemm(const float* __restrict__ A, const float* __restrict__ W,
            const float* __restrict__ bias, float* __restrict__ C,
            int M, int N, int K, int ldw)
{
    __shared__ float As[16][132];
    __shared__ float Bs[16][132];
    const int tid = threadIdx.x;
    const int tx = tid & 15, ty = tid >> 4;
    const int m0 = blockIdx.y * 128, n0 = blockIdx.x * 128;
    const int lr = tid >> 2, lc = (tid & 3) * 4;

    u64 acc[8][4];
    #pragma unroll
    for (int i = 0; i < 8; i++)
        #pragma unroll
        for (int j = 0; j < 4; j++) acc[i][j] = 0ULL;

    for (int k0 = 0; k0 < K; k0 += 16) {
        #pragma unroll
        for (int h = 0; h < 2; h++) {
            int m = m0 + lr + h*64;
            float4 v = (m < M) ? *(const float4*)(A + (size_t)m*K + k0 + lc)
                               : make_float4(0.f,0.f,0.f,0.f);
            As[lc+0][lr+h*64] = v.x; As[lc+1][lr+h*64] = v.y;
            As[lc+2][lr+h*64] = v.z; As[lc+3][lr+h*64] = v.w;
        }
        #pragma unroll
        for (int h = 0; h < 2; h++) {
            int n = n0 + lr + h*64;
            float4 v = *(const float4*)(W + (size_t)n*ldw + k0 + lc);
            Bs[lc+0][lr+h*64] = v.x; Bs[lc+1][lr+h*64] = v.y;
            Bs[lc+2][lr+h*64] = v.z; Bs[lc+3][lr+h*64] = v.w;
        }
        __syncthreads();
        #pragma unroll
        for (int k = 0; k < 16; k++) {
            float4 a0 = *(const float4*)&As[k][ty*8];
            float4 a1 = *(const float4*)&As[k][ty*8+4];
            float4 b0 = *(const float4*)&Bs[k][tx*8];
            float4 b1 = *(const float4*)&Bs[k][tx*8+4];
            float ra[8] = {a0.x,a0.y,a0.z,a0.w,a1.x,a1.y,a1.z,a1.w};
            u64 bp[4];
            bp[0] = f2pack(b0.x, b0.y); bp[1] = f2pack(b0.z, b0.w);
            bp[2] = f2pack(b1.x, b1.y); bp[3] = f2pack(b1.z, b1.w);
            #pragma unroll
            for (int i = 0; i < 8; i++) {
                u64 ap = f2pack(ra[i], ra[i]);
                f2fma(acc[i][0], ap, bp[0]); f2fma(acc[i][1], ap, bp[1]);
                f2fma(acc[i][2], ap, bp[2]); f2fma(acc[i][3], ap, bp[3]);
            }
        }
        __syncthreads();
    }
    #pragma unroll
    for (int i = 0; i < 8; i++) {
        int m = m0 + ty*8 + i;
        if (m >= M) continue;
        float* crow = C + (size_t)m*N;
        int nc = n0 + tx*8;
        #pragma unroll
        for (int j = 0; j < 4; j++) {
            float2 v = f2unpack(acc[i][j]);
            float c0 = v.x, c1 = v.y;
            if (bias) { c0 += bias[nc+2*j]; c1 += bias[nc+2*j+1]; }
            crow[nc+2*j] = c0; crow[nc+2*j+1] = c1;
        }
    }
}

// ---------------- persistent encoder ----------------
__global__ __launch_bounds__(256)
void k_enc(const float* __restrict__ Wf, const float* __restrict__ bf,
           const float* __restrict__ Wb, const float* __restrict__ bb,
           const int* __restrict__ len)
{
    __shared__ float hs[16*HP_];
    const int blk = blockIdx.x;
    const int dir = blk >> 5, jb = blk & 31;
    const int tid = threadIdx.x;
    const int b = tid & 15;
    const int j = jb*16 + (tid >> 4);
    const float* Whh = dir ? Wb : Wf;
    const float* bhh = dir ? bb : bf;
    float* hbase = dir ? g_hb : g_hf;
    const float* GIb = dir ? g_GI_b : g_GI_f;
    const int L = len[b];
    const float* Wr = Whh + (size_t)j*H_;
    const float* Wz = Wr + (size_t)H_*H_;
    const float* Wn = Wz + (size_t)H_*H_;
    const float br = bhh[j], bz = bhh[H_+j], bn = bhh[2*H_+j];
    unsigned* cnt = &g_gb[dir].cnt;
    unsigned* gen = &g_gb[dir].gen;

    for (int t = 0; t < S_; t++) {
        const float* hrow = hbase + (t & 1)*(B_*H_);
        for (int idx = tid; idx < B_*H_; idx += 256)
            hs[(idx >> 9)*HP_ + (idx & 511)] = hrow[idx];
        __syncthreads();

        float ar, az, an;
        dot3_512(hs + b*HP_, Wr, Wz, Wn, ar, az, an);
        const float* GI = GIb + ((size_t)(b*S_ + t))*H3_;
        float r = sigf(GI[j]       + ar + br);
        float z = sigf(GI[H_+j]    + az + bz);
        float n = tanhf(GI[2*H_+j] + r*(an + bn));
        float hold = hs[b*HP_ + j];
        float hnew = (1.f - z)*n + z*hold;
        bool valid = t < L;
        hbase[((t+1) & 1)*(B_*H_) + b*H_ + j] = valid ? hnew : hold;
        float o = valid ? hnew : 0.f;
        if (dir == 0) g_enc_out[((size_t)(b*S_+t))*H2_ + j] = o;
        else          g_out_bR [((size_t)(b*S_+t))*H_  + j] = o;
        gbar2(cnt, gen, (unsigned)(t + 1), 32u);
    }
}

__global__ void k_outbw(const int* __restrict__ len)
{
    int i = blockIdx.x*blockDim.x + threadIdx.x;
    if (i >= B_*S_*H_) return;
    int j = i % H_, s = (i / H_) % S_, b = i / (H_*S_);
    int L = len[b];
    int r = (s < L) ? (L-1-s) : s;
    g_enc_out[((size_t)(b*S_+s))*H2_ + H_ + j] = g_out_bR[((size_t)(b*S_+r))*H_ + j];
}

__global__ void k_bridge(const float* __restrict__ bridge_W, const float* __restrict__ bridge_b)
{
    const int tid = threadIdx.x;
    const int b = tid & 15, j = blockIdx.x * 16 + (tid >> 4);
    const float* Wrow = bridge_W + (size_t)j*H2_;
    const float* hf = g_hf + b*H_;
    const float* hb = g_hb + b*H_;
    float acc = 0.f;
    #pragma unroll 4
    for (int k = 0; k < H_; k += 4) {
        float4 h = *(const float4*)(hf + k);
        float4 w = *(const float4*)(Wrow + k);
        acc = fmaf(h.x,w.x, fmaf(h.y,w.y, fmaf(h.z,w.z, fmaf(h.w,w.w, acc))));
    }
    #pragma unroll 4
    for (int k = 0; k < H_; k += 4) {
        float4 h = *(const float4*)(hb + k);
        float4 w = *(const float4*)(Wrow + H_ + k);
        acc = fmaf(h.x,w.x, fmaf(h.y,w.y, fmaf(h.z,w.z, fmaf(h.w,w.w, acc))));
    }
    g_hdec[b*H_ + j] = tanhf(acc + bridge_b[j]);
}

// ---------------- persistent decoder segment [t0, t1) ----------------
__global__ __launch_bounds__(512)
void k_dec(const float* __restrict__ Wa_dec, const float* __restrict__ Wv,
           const int* __restrict__ src, const float* __restrict__ Whd,
           const float* __restrict__ bhd, int t0, int t1, unsigned eraBase)
{
    __shared__ float hs[16*HP_];
    __shared__ float esm[S_], asmx[S_];
    const int blk = blockIdx.x, tid = threadIdx.x;
    const int lane = tid & 31, w = tid >> 5;
    const int gw = blk*16 + w;
    const int j = gw >> 1;
    const int b8 = ((gw & 1) << 3) + (lane >> 2);
    const int kq = lane & 3;
    const int bq_b = blk >> 2, bq_q = blk & 3;
    unsigned* cnt = &g_gb[2].cnt;
    unsigned* gen = &g_gb[2].gen;
    unsigned era = eraBase;

    const int c0 = bq_q*640 + tid;
    const bool h1 = tid < 128;
    const int c1 = bq_q*640 + 512 + tid;
    const float *p0base, *p1base = 0; int st0, st1 = 0;
    int d0kind, d0off, d1kind = 0, d1off = 0;
    if (c0 < H2_) { p0base = g_enc_out + (size_t)bq_b*S_*H2_ + c0; st0 = H2_; d0kind = 0; d0off = c0; }
    else { int cc = c0 - H2_; p0base = g_encW + (size_t)bq_b*S_*H3_ + cc; st0 = H3_; d0kind = 1; d0off = cc; }
    if (h1) {
        if (c1 < H2_) { p1base = g_enc_out + (size_t)bq_b*S_*H2_ + c1; st1 = H2_; d1kind = 0; d1off = c1; }
        else { int cc = c1 - H2_; p1base = g_encW + (size_t)bq_b*S_*H3_ + cc; st1 = H3_; d1kind = 1; d1off = cc; }
    }

    for (int t = t0; t < t1; t++) {
        const float* hrow = g_hdec + (t & 1)*(B_*H_);
        for (int idx = tid; idx < B_*H_; idx += 512)
            hs[(idx >> 9)*HP_ + (idx & 511)] = hrow[idx];
        __syncthreads();

        // P1: dp
        {
            const float* wa = Wa_dec + (size_t)j*H_ + kq*128;
            const float* x  = hs + b8*HP_ + kq*128;
            u64 a0 = 0, a1 = 0;
            #pragma unroll
            for (int k = 0; k < 128; k += 4) {
                float4 xv = *(const float4*)(x + k);
                float4 wv = *(const float4*)(wa + k);
                f2fma(a0, f2pack(xv.x, xv.y), f2pack(wv.x, wv.y));
                f2fma(a1, f2pack(xv.z, xv.w), f2pack(wv.z, wv.w));
            }
            float2 p = f2unpack(a0), q2 = f2unpack(a1);
            float s = (p.x + q2.x) + (p.y + q2.y);
            s += __shfl_xor_sync(0xffffffffu, s, 1);
            s += __shfl_xor_sync(0xffffffffu, s, 2);
            if (kq == 0) g_dps[b8*H_ + j] = s;
        }
        gbar2(cnt, gen, ++era, 64u);

        // P2: energies + softmax + ctx/gic
        {
            const float* dp = g_dps + bq_b*H_;
            #pragma unroll
            for (int i = 0; i < 8; i++) {
                int s = w*8 + i;
                const float* er = g_encP + ((size_t)(bq_b*S_ + s))*H_;
                float acc = 0.f;
                #pragma unroll
                for (int ii = 0; ii < 16; ii++) {
                    int k = lane + 32*ii;
                    acc = fmaf(tanhap(er[k] + dp[k]), Wv[k], acc);
                }
                #pragma unroll
                for (int o = 16; o; o >>= 1) acc += __shfl_xor_sync(0xffffffffu, acc, o);
                if (lane == 0)
                    esm[s] = (src[bq_b*S_ + s] != 0) ? acc : -1e9f;
            }
            __syncthreads();
            if (w == 0) {
                float v[4]; float m = -1e30f;
                #pragma unroll
                for (int i = 0; i < 4; i++) { v[i] = esm[lane + 32*i]; m = fmaxf(m, v[i]); }
                #pragma unroll
                for (int o = 16; o; o >>= 1) m = fmaxf(m, __shfl_xor_sync(0xffffffffu, m, o));
                float sum = 0.f;
                #pragma unroll
                for (int i = 0; i < 4; i++) { v[i] = expf(v[i] - m); sum += v[i]; }
                #pragma unroll
                for (int o = 16; o; o >>= 1) sum += __shfl_xor_sync(0xffffffffu, sum, o);
                float inv = 1.f / sum;
                #pragma unroll
                for (int i = 0; i < 4; i++) asmx[lane + 32*i] = v[i]*inv;
            }
            __syncthreads();
            float a0 = 0.f, a0b = 0.f, a1 = 0.f, a1b = 0.f;
            #pragma unroll 8
            for (int s = 0; s < 64; s++) {
                float wA = asmx[s], wB = asmx[s + 64];
                a0  = fmaf(wA, p0base[(size_t)s*st0], a0);
                a0b = fmaf(wB, p0base[(size_t)(s + 64)*st0], a0b);
                if (h1) {
                    a1  = fmaf(wA, p1base[(size_t)s*st1], a1);
                    a1b = fmaf(wB, p1base[(size_t)(s + 64)*st1], a1b);
                }
            }
            a0 += a0b; a1 += a1b;
            size_t n = (size_t)t*B_ + bq_b;
            float* d0 = d0kind ? (g_gict + bq_b*H3_ + d0off) : (g_feat + n*KO_ + H_ + d0off);
            *d0 = a0;
            if (h1) {
                float* d1 = d1kind ? (g_gict + bq_b*H3_ + d1off) : (g_feat + n*KO_ + H_ + d1off);
                *d1 = a1;
            }
        }
        gbar2(cnt, gen, ++era, 64u);

        // P3: GRU
        {
            const float* Wr = Whd + (size_t)j*H_ + kq*128;
            const float* Wz = Whd + (size_t)(H_+j)*H_ + kq*128;
            const float* Wn = Whd + (size_t)(2*H_+j)*H_ + kq*128;
            float ar, az, an;
            dot3_128(hs + b8*HP_ + kq*128, Wr, Wz, Wn, ar, az, an);
            ar += __shfl_xor_sync(0xffffffffu, ar, 1);
            ar += __shfl_xor_sync(0xffffffffu, ar, 2);
            az += __shfl_xor_sync(0xffffffffu, az, 1);
            az += __shfl_xor_sync(0xffffffffu, az, 2);
            an += __shfl_xor_sync(0xffffffffu, an, 1);
            an += __shfl_xor_sync(0xffffffffu, an, 2);
            if (kq == 0) {
                size_t n = (size_t)t*B_ + b8;
                const float* gie = g_GIe + n*H3_;
                const float* gic = g_gict + b8*H3_;
                float r  = sigf(gie[j]       + gic[j]       + ar + bhd[j]);
                float z  = sigf(gie[H_+j]    + gic[H_+j]    + az + bhd[H_+j]);
                float nn = tanhf(gie[2*H_+j] + gic[2*H_+j]  + r*(an + bhd[2*H_+j]));
                float hold = hs[b8*HP_ + j];
                float hnew = (1.f - z)*nn + z*hold;
                g_hdec[((t+1) & 1)*(B_*H_) + b8*H_ + j] = hnew;
                g_feat[n*KO_ + j] = hnew;
            }
        }
        gbar2(cnt, gen, ++era, 64u);
    }
}

extern "C" void kernel_launch(void* const* d_in, const int* in_sizes, int n_in,
                              void* d_out, int out_size)
{
    const int*   src      = (const int*)d_in[0];
    const int*   len      = (const int*)d_in[1];
    const int*   tgt      = (const int*)d_in[2];
    const float* enc_emb  = (const float*)d_in[3];
    const float* W_ih_f   = (const float*)d_in[4];
    const float* W_hh_f   = (const float*)d_in[5];
    const float* b_ih_f   = (const float*)d_in[6];
    const float* b_hh_f   = (const float*)d_in[7];
    const float* W_ih_b   = (const float*)d_in[8];
    const float* W_hh_b   = (const float*)d_in[9];
    const float* b_ih_b   = (const float*)d_in[10];
    const float* b_hh_b   = (const float*)d_in[11];
    const float* bridge_W = (const float*)d_in[12];
    const float* bridge_b = (const float*)d_in[13];
    const float* dec_emb  = (const float*)d_in[14];
    const float* Wa_enc   = (const float*)d_in[15];
    const float* Wa_dec   = (const float*)d_in[16];
    const float* Wv       = (const float*)d_in[17];
    const float* W_ih_d   = (const float*)d_in[18];
    const float* W_hh_d   = (const float*)d_in[19];
    const float* b_ih_d   = (const float*)d_in[20];
    const float* b_hh_d   = (const float*)d_in[21];
    const float* out_W    = (const float*)d_in[22];
    const float* out_b    = (const float*)d_in[23];
    float* out = (float*)d_out;

    float *p_emb, *p_emb_rev, *p_emb_in, *p_GI_f, *p_GI_b, *p_GIe, *p_enc_out, *p_encP, *p_encW;
    cudaGetSymbolAddress((void**)&p_emb,     g_emb);
    cudaGetSymbolAddress((void**)&p_emb_rev, g_emb_rev);
    cudaGetSymbolAddress((void**)&p_emb_in,  g_emb_in);
    cudaGetSymbolAddress((void**)&p_GI_f,    g_GI_f);
    cudaGetSymbolAddress((void**)&p_GI_b,    g_GI_b);
    cudaGetSymbolAddress((void**)&p_GIe,     g_GIe);
    cudaGetSymbolAddress((void**)&p_enc_out, g_enc_out);
    cudaGetSymbolAddress((void**)&p_encP,    g_encP);
    cudaGetSymbolAddress((void**)&p_encW,    g_encW);

    static cudaStream_t sB = 0;
    static cudaEvent_t e1 = 0, e2 = 0, e3 = 0, e4 = 0;
    if (!sB) {
        int lo, hi;
        cudaDeviceGetStreamPriorityRange(&lo, &hi);
        cudaStreamCreateWithPriority(&sB, cudaStreamNonBlocking, lo);
        cudaEventCreateWithFlags(&e1, cudaEventDisableTiming);
        cudaEventCreateWithFlags(&e2, cudaEventDisableTiming);
        cudaEventCreateWithFlags(&e3, cudaEventDisableTiming);
        cudaEventCreateWithFlags(&e4, cudaEventDisableTiming);
    }

    cudaFuncSetAttribute(k_outgemm, cudaFuncAttributeMaxDynamicSharedMemorySize, 3*STG_SZ);

    // main stream: gather -> encoder chain
    k_gather<<<512, 256>>>(src, len, tgt, enc_emb, dec_emb);
    cudaEventRecord(e1, 0);

    // side stream: convW + decoder-embedding GEMM, concurrent with encoder
    cudaStreamWaitEvent(sB, e1, 0);
    k_convW<<<1024, 256, 0, sB>>>(out_W);
    k_gemm<<<dim3(H3_/128, (ST_*B_+127)/128), 256, 0, sB>>>(p_emb_in, W_ih_d, b_ih_d, p_GIe, ST_*B_, H3_, E_, KD_);
    cudaEventRecord(e2, sB);

    k_gemm<<<dim3(H3_/128, (B_*S_)/128), 256>>>(p_emb,     W_ih_f, b_ih_f, p_GI_f, B_*S_, H3_, E_, E_);
    k_gemm<<<dim3(H3_/128, (B_*S_)/128), 256>>>(p_emb_rev, W_ih_b, b_ih_b, p_GI_b, B_*S_, H3_, E_, E_);
    k_enc<<<64, 256>>>(W_hh_f, b_hh_f, W_hh_b, b_hh_b, len);
    k_outbw<<<(B_*S_*H_)/256, 256>>>(len);
    k_bridge<<<H_/16, 256>>>(bridge_W, bridge_b);
    k_gemm<<<dim3(H_/128, (B_*S_)/128), 256>>>(p_enc_out, Wa_enc, 0, p_encP, B_*S_, H_, H2_, H2_);
    k_gemm<<<dim3(H3_/128, (B_*S_)/128), 256>>>(p_enc_out, W_ih_d + E_, 0, p_encW, B_*S_, H3_, H2_, KD_);

    // decoder part 1 (needs GIe from side stream)
    cudaStreamWaitEvent(0, e2, 0);
    k_dec<<<64, 512>>>(Wa_dec, Wv, src, W_hh_d, b_hh_d, 0, TSPLIT_, 0u);
    cudaEventRecord(e3, 0);

    // side stream: first-half conversion + output GEMM, concurrent with decoder part 2
    cudaStreamWaitEvent(sB, e3, 0);
    k_convA<<<512, 256, 0, sB>>>(0, TSPLIT_*B_);
    k_outgemm<<<dim3(TSPLIT_*B_/256, V_/128), 256, 3*STG_SZ, sB>>>(out, out_b, 0);
    cudaEventRecord(e4, sB);

    // decoder part 2 + second-half output GEMM
    k_dec<<<64, 512>>>(Wa_dec, Wv, src, W_hh_d, b_hh_d, TSPLIT_, ST_, 3u*TSPLIT_);
    k_convA<<<512, 256>>>(TSPLIT_*B_, MPAD_);
    k_outgemm<<<dim3((MPAD_ - TSPLIT_*B_)/256, V_/128), 256, 3*STG_SZ>>>(out, out_b, TSPLIT_*B_/256);

    cudaStreamWaitEvent(0, e4, 0);
}

// round 15
// speedup vs baseline: 1.1153x; 1.1153x over previous
#include <cuda_runtime.h>
#include <cuda_bf16.h>

#define B_  16
#define S_  128
#define T_  128
#define ST_ 127
#define E_  256
#define H_  512
#define H2_ 1024
#define H3_ 1536
#define KD_ 1280
#define KO_ 1792
#define V_  32000
#define MPAD_ 2048
#define K3_ (3*KO_)
#define HP_ 516
#define NCH_ 168
#define STG_A 20480
#define STG_B 10240
#define TILE_SZ 20480

typedef unsigned int u32;
typedef unsigned long long u64;

__device__ float g_emb    [B_*S_*E_];
__device__ float g_emb_rev[B_*S_*E_];
__device__ float g_emb_in [ST_*B_*E_];
__device__ float g_GI_f   [B_*S_*H3_];
__device__ float g_GI_b   [B_*S_*H3_];
__device__ float g_GIe    [ST_*B_*H3_];
__device__ float g_enc_out[B_*S_*H2_];
__device__ float g_out_bR [B_*S_*H_];
__device__ float g_encP   [B_*S_*H_];
__device__ float g_encW   [B_*S_*H3_];
__device__ float g_feat   [ST_*B_*KO_];
__device__ float g_hf  [2*B_*H_];
__device__ float g_hb  [2*B_*H_];
__device__ float g_hdec[2*B_*H_];
__device__ float g_dps [B_*H_];
__device__ float g_gict[B_*H3_];
__device__ __align__(16) unsigned char g_A3p[(size_t)8*NCH_*STG_A];
__device__ __align__(16) unsigned char g_B3p[(size_t)250*NCH_*STG_B];

struct GBS { unsigned cnt; unsigned p0[31]; unsigned gen; unsigned p1[31]; };
__device__ GBS g_gb[3];

__device__ __forceinline__ void gbar2(unsigned* cnt, unsigned* gen, unsigned era, unsigned nb) {
    __syncthreads();
    if (threadIdx.x == 0) {
        unsigned prev;
        asm volatile("atom.add.acq_rel.gpu.global.u32 %0, [%1], 1;"
                     : "=r"(prev) : "l"(cnt) : "memory");
        if (prev == era*nb - 1u) {
            asm volatile("st.release.gpu.global.u32 [%0], %1;" :: "l"(gen), "r"(era) : "memory");
        } else {
            unsigned g;
            do {
                asm volatile("ld.acquire.gpu.global.u32 %0, [%1];" : "=r"(g) : "l"(gen) : "memory");
            } while (g < era);
        }
    }
    __syncthreads();
}

__device__ __forceinline__ float sigf(float x) { return 1.f / (1.f + expf(-x)); }
__device__ __forceinline__ float tanhap(float x) {
    float y; asm("tanh.approx.f32 %0, %1;" : "=f"(y) : "f"(x)); return y;
}
__device__ __forceinline__ u64 f2pack(float a, float b) {
    u64 r; asm("mov.b64 %0, {%1, %2};" : "=l"(r) : "r"(__float_as_uint(a)), "r"(__float_as_uint(b)));
    return r;
}
__device__ __forceinline__ void f2fma(u64& d, u64 a, u64 b) {
    asm("fma.rn.f32x2 %0, %1, %2, %0;" : "+l"(d) : "l"(a), "l"(b));
}
__device__ __forceinline__ float2 f2unpack(u64 v) {
    unsigned lo, hi; asm("mov.b64 {%0, %1}, %2;" : "=r"(lo), "=r"(hi) : "l"(v));
    return make_float2(__uint_as_float(lo), __uint_as_float(hi));
}
__device__ __forceinline__ void dot3_512(const float* __restrict__ x,
    const float* __restrict__ r0, const float* __restrict__ r1,
    const float* __restrict__ r2, float& o0, float& o1, float& o2)
{
    u64 a0=0,a1=0,b0=0,b1=0,c0=0,c1=0;
    #pragma unroll 8
    for (int k = 0; k < H_; k += 4) {
        float4 xv = *(const float4*)(x + k);
        u64 xlo = f2pack(xv.x, xv.y), xhi = f2pack(xv.z, xv.w);
        float4 w0 = *(const float4*)(r0 + k);
        f2fma(a0, xlo, f2pack(w0.x, w0.y)); f2fma(a1, xhi, f2pack(w0.z, w0.w));
        float4 w1 = *(const float4*)(r1 + k);
        f2fma(b0, xlo, f2pack(w1.x, w1.y)); f2fma(b1, xhi, f2pack(w1.z, w1.w));
        float4 w2 = *(const float4*)(r2 + k);
        f2fma(c0, xlo, f2pack(w2.x, w2.y)); f2fma(c1, xhi, f2pack(w2.z, w2.w));
    }
    float2 p, q;
    p = f2unpack(a0); q = f2unpack(a1); o0 = (p.x + q.x) + (p.y + q.y);
    p = f2unpack(b0); q = f2unpack(b1); o1 = (p.x + q.x) + (p.y + q.y);
    p = f2unpack(c0); q = f2unpack(c1); o2 = (p.x + q.x) + (p.y + q.y);
}
__device__ __forceinline__ void dot3_128(const float* __restrict__ x,
    const float* __restrict__ r0, const float* __restrict__ r1,
    const float* __restrict__ r2, float& o0, float& o1, float& o2)
{
    u64 a0=0,a1=0,b0=0,b1=0,c0=0,c1=0;
    #pragma unroll
    for (int k = 0; k < 128; k += 4) {
        float4 xv = *(const float4*)(x + k);
        u64 xlo = f2pack(xv.x, xv.y), xhi = f2pack(xv.z, xv.w);
        float4 w0 = *(const float4*)(r0 + k);
        f2fma(a0, xlo, f2pack(w0.x, w0.y)); f2fma(a1, xhi, f2pack(w0.z, w0.w));
        float4 w1 = *(const float4*)(r1 + k);
        f2fma(b0, xlo, f2pack(w1.x, w1.y)); f2fma(b1, xhi, f2pack(w1.z, w1.w));
        float4 w2 = *(const float4*)(r2 + k);
        f2fma(c0, xlo, f2pack(w2.x, w2.y)); f2fma(c1, xhi, f2pack(w2.z, w2.w));
    }
    float2 p, q;
    p = f2unpack(a0); q = f2unpack(a1); o0 = (p.x + q.x) + (p.y + q.y);
    p = f2unpack(b0); q = f2unpack(b1); o1 = (p.x + q.x) + (p.y + q.y);
    p = f2unpack(c0); q = f2unpack(c1); o2 = (p.x + q.x) + (p.y + q.y);
}

__device__ __forceinline__ u32 s2u(const void* p) {
    u32 a; asm("{ .reg .u64 t; cvta.to.shared.u64 t, %1; cvt.u32.u64 %0, t; }" : "=r"(a) : "l"(p));
    return a;
}
__device__ __forceinline__ void ldmA4(u32 addr, u32* a) {
    asm volatile("ldmatrix.sync.aligned.m8n8.x4.shared.b16 {%0,%1,%2,%3}, [%4];"
        : "=r"(a[0]), "=r"(a[1]), "=r"(a[2]), "=r"(a[3]) : "r"(addr));
}
__device__ __forceinline__ void ldmB2(u32 addr, u32* b) {
    asm volatile("ldmatrix.sync.aligned.m8n8.x2.shared.b16 {%0,%1}, [%2];"
        : "=r"(b[0]), "=r"(b[1]) : "r"(addr));
}
__device__ __forceinline__ void mma16816(float* c, const u32* a, const u32* b) {
    asm volatile("mma.sync.aligned.m16n8k16.row.col.f32.bf16.bf16.f32 "
        "{%0,%1,%2,%3}, {%4,%5,%6,%7}, {%8,%9}, {%0,%1,%2,%3};"
        : "+f"(c[0]), "+f"(c[1]), "+f"(c[2]), "+f"(c[3])
        : "r"(a[0]), "r"(a[1]), "r"(a[2]), "r"(a[3]), "r"(b[0]), "r"(b[1]));
}

#define MB_INIT(mb, c)   asm volatile("mbarrier.init.shared.b64 [%0], %1;" :: "r"((u32)(mb)), "r"((u32)(c)) : "memory")
#define MB_EXPECT_TX(mb, n) asm volatile("mbarrier.arrive.expect_tx.shared.b64 _, [%0], %1;" :: "r"((u32)(mb)), "r"((u32)(n)) : "memory")
#define BULK_G2S(dst, src, n, mb) \
    asm volatile("cp.async.bulk.shared::cluster.global.mbarrier::complete_tx::bytes [%0], [%1], %2, [%3];" \
        :: "r"((u32)(dst)), "l"(src), "r"((u32)(n)), "r"((u32)(mb)) : "memory")
#define MB_WAIT(mbar, par) do { \
    u32 _m = (u32)(mbar); u32 _p = (u32)(par); u32 _d; \
    asm volatile("{\n\t.reg .pred p;\n\t" \
        "mbarrier.try_wait.parity.acquire.cta.shared::cta.b64 p, [%1], %2;\n\t" \
        "selp.b32 %0, 1, 0, p;\n\t}" : "=r"(_d) : "r"(_m), "r"(_p) : "memory"); \
    if (!_d) { \
        asm volatile("{\n\t.reg .pred P1;\n\t" \
            "WL_%=:\n\t" \
            "mbarrier.try_wait.parity.acquire.cta.shared::cta.b64 P1, [%0], %1, 0x989680;\n\t" \
            "@P1 bra.uni WD_%=;\n\tbra.uni WL_%=;\n\tWD_%=:\n\t}" \
            :: "r"(_m), "r"(_p) : "memory"); \
    } } while (0)

// ---------------- gathers + init ----------------
__global__ void k_gather(const int* __restrict__ src, const int* __restrict__ len,
                         const int* __restrict__ tgt,
                         const float* __restrict__ enc_emb, const float* __restrict__ dec_emb)
{
    if (blockIdx.x == 0 && threadIdx.x == 0) {
        #pragma unroll
        for (int i = 0; i < 3; i++) { g_gb[i].cnt = 0u; g_gb[i].gen = 0u; }
        __threadfence();
    }
    const int total = B_*S_*E_;
    for (int i = blockIdx.x*blockDim.x + threadIdx.x; i < total; i += gridDim.x*blockDim.x) {
        int e = i % E_, s = (i / E_) % S_, b = i / (E_*S_);
        int L = len[b];
        g_emb[i] = enc_emb[(size_t)src[b*S_+s]*E_ + e];
        int r = (s < L) ? (L-1-s) : s;
        g_emb_rev[i] = enc_emb[(size_t)src[b*S_+r]*E_ + e];
        if (s < ST_) {
            float v = dec_emb[(size_t)tgt[b*T_+s]*E_ + e];
            size_t n = (size_t)s*B_ + b;
            g_emb_in[n*E_ + e] = v;
            g_feat[n*KO_ + (H_+H2_) + e] = v;
        }
        if (i < 2*B_*H_) { g_hf[i] = 0.f; g_hb[i] = 0.f; }
    }
}

// ---------------- packed bf16 hi/lo conversions ----------------
__device__ __forceinline__ u32 pack_bf2(float a0, float a1) {
    __nv_bfloat16 h0 = __float2bfloat16(a0), h1 = __float2bfloat16(a1);
    return (u32)__bfloat16_as_ushort(h0) | ((u32)__bfloat16_as_ushort(h1) << 16);
}
__device__ __forceinline__ u32 pack_bf2lo(float a0, float a1) {
    __nv_bfloat16 h0 = __float2bfloat16(a0), h1 = __float2bfloat16(a1);
    float l0 = a0 - __bfloat162float(h0), l1 = a1 - __bfloat162float(h1);
    return (u32)__bfloat16_as_ushort(__float2bfloat16(l0))
         | ((u32)__bfloat16_as_ushort(__float2bfloat16(l1)) << 16);
}
__global__ void k_convW(const float* __restrict__ W)
{
    const int NKG = KO_/8;
    const size_t total = (size_t)V_*NKG;
    for (size_t i = (size_t)blockIdx.x*blockDim.x + threadIdx.x; i < total;
         i += (size_t)gridDim.x*blockDim.x) {
        int n = (int)(i / NKG), k = (int)(i % NKG) * 8;
        const float* wp = W + (size_t)n*KO_ + k;
        float4 v0 = *(const float4*)(wp), v1 = *(const float4*)(wp + 4);
        uint4 hi, lo;
        hi.x = pack_bf2(v0.x, v0.y); hi.y = pack_bf2(v0.z, v0.w);
        hi.z = pack_bf2(v1.x, v1.y); hi.w = pack_bf2(v1.z, v1.w);
        lo.x = pack_bf2lo(v0.x, v0.y); lo.y = pack_bf2lo(v0.z, v0.w);
        lo.z = pack_bf2lo(v1.x, v1.y); lo.w = pack_bf2lo(v1.z, v1.w);
        int nb = n >> 7, r = n & 127;
        #pragma unroll
        for (int t3 = 0; t3 < 3; t3++) {
            int k3 = t3*KO_ + k;
            size_t off = (((size_t)nb*NCH_ + (k3 >> 5))*128 + r)*80 + (k3 & 31)*2;
            *(uint4*)(g_B3p + off) = (t3 == 1) ? lo : hi;
        }
    }
}
__global__ void k_convA()
{
    const int NKG = KO_/8;
    const size_t total = (size_t)MPAD_*NKG;
    for (size_t i = (size_t)blockIdx.x*blockDim.x + threadIdx.x; i < total;
         i += (size_t)gridDim.x*blockDim.x) {
        int m = (int)(i / NKG), k = (int)(i % NKG) * 8;
        float4 v0 = make_float4(0.f,0.f,0.f,0.f), v1 = v0;
        if (m < ST_*B_) {
            const float* ap = g_feat + (size_t)m*KO_ + k;
            v0 = *(const float4*)(ap); v1 = *(const float4*)(ap + 4);
        }
        uint4 hi, lo;
        hi.x = pack_bf2(v0.x, v0.y); hi.y = pack_bf2(v0.z, v0.w);
        hi.z = pack_bf2(v1.x, v1.y); hi.w = pack_bf2(v1.z, v1.w);
        lo.x = pack_bf2lo(v0.x, v0.y); lo.y = pack_bf2lo(v0.z, v0.w);
        lo.z = pack_bf2lo(v1.x, v1.y); lo.w = pack_bf2lo(v1.z, v1.w);
        int mb = m >> 8, r = m & 255;
        #pragma unroll
        for (int t3 = 0; t3 < 3; t3++) {
            int k3 = t3*KO_ + k;
            size_t off = (((size_t)mb*NCH_ + (k3 >> 5))*256 + r)*80 + (k3 & 31)*2;
            *(uint4*)(g_A3p + off) = (t3 == 2) ? lo : hi;
        }
    }
}

// ---------------- HMMA output GEMM: 128x128 tile, 2 CTAs/SM, bulk 3-stage ----------------
__global__ __launch_bounds__(256, 2)
void k_outgemm(float* __restrict__ out, const float* __restrict__ bias)
{
    __shared__ __align__(16) char sm[3*TILE_SZ];
    __shared__ __align__(8) u64 mbar[3];
    const int tid = threadIdx.x, wid = tid >> 5, lane = tid & 31;
    const int wm = wid >> 2, wn = wid & 3;   // 2 x 4 warps, warp tile 64x32
    const int bx = blockIdx.x, by = blockIdx.y;
    const int m0 = bx * 128, n0 = by * 128;

    if (tid < 3) MB_INIT(s2u(&mbar[tid]), 1);
    __syncthreads();

    float acc[4][4][4];
    #pragma unroll
    for (int i = 0; i < 4; i++)
        #pragma unroll
        for (int j = 0; j < 4; j++)
            #pragma unroll
            for (int q = 0; q < 4; q++) acc[i][j][q] = 0.f;

    auto issue = [&](int c) {
        int slot = c % 3;
        u32 mb = s2u(&mbar[slot]);
        MB_EXPECT_TX(mb, TILE_SZ);
        u32 da = s2u(sm + slot*TILE_SZ);
        // A slab: rows [m0, m0+128) live inside the 256-row packed block
        const unsigned char* ga = g_A3p + ((size_t)(bx >> 1)*NCH_ + c)*STG_A + (size_t)(bx & 1)*10240;
        const unsigned char* gb = g_B3p + ((size_t)by*NCH_ + c)*STG_B;
        BULK_G2S(da, ga, 10240, mb);
        BULK_G2S(da + 10240, gb, 10240, mb);
    };
    if (tid == 0) { issue(0); issue(1); }

    const int NC = NCH_;
    for (int c = 0; c < NC; c++) {
        MB_WAIT(s2u(&mbar[c % 3]), (c/3) & 1);
        if (tid == 0 && c + 2 < NC) issue(c + 2);
        char* base = sm + (c % 3)*TILE_SZ;
        const u32 aB = s2u(base), bB = s2u(base + 10240);
        #pragma unroll
        for (int ks = 0; ks < 2; ks++) {
            u32 af[4][4], bf[4][2];
            #pragma unroll
            for (int fm = 0; fm < 4; fm++)
                ldmA4(aB + (u32)((wm*64 + fm*16 + (lane & 15))*80 + ks*32 + (lane >> 4)*16), af[fm]);
            #pragma unroll
            for (int fn = 0; fn < 4; fn++)
                ldmB2(bB + (u32)((wn*32 + fn*8 + (lane & 7))*80 + ks*32 + ((lane >> 3) & 1)*16), bf[fn]);
            #pragma unroll
            for (int fm = 0; fm < 4; fm++)
                #pragma unroll
                for (int fn = 0; fn < 4; fn++)
                    mma16816(acc[fm][fn], af[fm], bf[fn]);
        }
        __syncthreads();
    }

    #pragma unroll
    for (int fm = 0; fm < 4; fm++) {
        #pragma unroll
        for (int half = 0; half < 2; half++) {
            int m = m0 + wm*64 + fm*16 + (lane >> 2) + half*8;
            if (m >= ST_*B_) continue;
            float* orow = out + ((size_t)((m & 15)*ST_ + (m >> 4)))*V_;
            #pragma unroll
            for (int fn = 0; fn < 4; fn++) {
                int nc = n0 + wn*32 + fn*8 + (lane & 3)*2;
                float2 v;
                v.x = acc[fm][fn][half*2 + 0] + bias[nc];
                v.y = acc[fm][fn][half*2 + 1] + bias[nc + 1];
                *(float2*)(orow + nc) = v;
            }
        }
    }
}

// ---------------- SIMT f32 GEMM for the small matmuls ----------------
__global__ __launch_bounds__(256, 2)
void k_gemm(const float* __restrict__ A, const float* __restrict__ W,
            const float* __restrict__ bias, float* __restrict__ C,
            int M, int N, int K, int ldw)
{
    __shared__ float As[16][132];
    __shared__ float Bs[16][132];
    const int tid = threadIdx.x;
    const int tx = tid & 15, ty = tid >> 4;
    const int m0 = blockIdx.y * 128, n0 = blockIdx.x * 128;
    const int lr = tid >> 2, lc = (tid & 3) * 4;

    u64 acc[8][4];
    #pragma unroll
    for (int i = 0; i < 8; i++)
        #pragma unroll
        for (int j = 0; j < 4; j++) acc[i][j] = 0ULL;

    for (int k0 = 0; k0 < K; k0 += 16) {
        #pragma unroll
        for (int h = 0; h < 2; h++) {
            int m = m0 + lr + h*64;
            float4 v = (m < M) ? *(const float4*)(A + (size_t)m*K + k0 + lc)
                               : make_float4(0.f,0.f,0.f,0.f);
            As[lc+0][lr+h*64] = v.x; As[lc+1][lr+h*64] = v.y;
            As[lc+2][lr+h*64] = v.z; As[lc+3][lr+h*64] = v.w;
        }
        #pragma unroll
        for (int h = 0; h < 2; h++) {
            int n = n0 + lr + h*64;
            float4 v = *(const float4*)(W + (size_t)n*ldw + k0 + lc);
            Bs[lc+0][lr+h*64] = v.x; Bs[lc+1][lr+h*64] = v.y;
            Bs[lc+2][lr+h*64] = v.z; Bs[lc+3][lr+h*64] = v.w;
        }
        __syncthreads();
        #pragma unroll
        for (int k = 0; k < 16; k++) {
            float4 a0 = *(const float4*)&As[k][ty*8];
            float4 a1 = *(const float4*)&As[k][ty*8+4];
            float4 b0 = *(const float4*)&Bs[k][tx*8];
            float4 b1 = *(const float4*)&Bs[k][tx*8+4];
            float ra[8] = {a0.x,a0.y,a0.z,a0.w,a1.x,a1.y,a1.z,a1.w};
            u64 bp[4];
            bp[0] = f2pack(b0.x, b0.y); bp[1] = f2pack(b0.z, b0.w);
            bp[2] = f2pack(b1.x, b1.y); bp[3] = f2pack(b1.z, b1.w);
            #pragma unroll
            for (int i = 0; i < 8; i++) {
                u64 ap = f2pack(ra[i], ra[i]);
                f2fma(acc[i][0], ap, bp[0]); f2fma(acc[i][1], ap, bp[1]);
                f2fma(acc[i][2], ap, bp[2]); f2fma(acc[i][3], ap, bp[3]);
            }
        }
        __syncthreads();
    }
    #pragma unroll
    for (int i = 0; i < 8; i++) {
        int m = m0 + ty*8 + i;
        if (m >= M) continue;
        float* crow = C + (size_t)m*N;
        int nc = n0 + tx*8;
        #pragma unroll
        for (int j = 0; j < 4; j++) {
            float2 v = f2unpack(acc[i][j]);
            float c0 = v.x, c1 = v.y;
            if (bias) { c0 += bias[nc+2*j]; c1 += bias[nc+2*j+1]; }
            crow[nc+2*j] = c0; crow[nc+2*j+1] = c1;
        }
    }
}

// ---------------- persistent encoder ----------------
__global__ __launch_bounds__(256)
void k_enc(const float* __restrict__ Wf, const float* __restrict__ bf,
           const float* __restrict__ Wb, const float* __restrict__ bb,
           const int* __restrict__ len)
{
    __shared__ float hs[16*HP_];
    const int blk = blockIdx.x;
    const int dir = blk >> 5, jb = blk & 31;
    const int tid = threadIdx.x;
    const int b = tid & 15;
    const int j = jb*16 + (tid >> 4);
    const float* Whh = dir ? Wb : Wf;
    const float* bhh = dir ? bb : bf;
    float* hbase = dir ? g_hb : g_hf;
    const float* GIb = dir ? g_GI_b : g_GI_f;
    const int L = len[b];
    const float* Wr = Whh + (size_t)j*H_;
    const float* Wz = Wr + (size_t)H_*H_;
    const float* Wn = Wz + (size_t)H_*H_;
    const float br = bhh[j], bz = bhh[H_+j], bn = bhh[2*H_+j];
    unsigned* cnt = &g_gb[dir].cnt;
    unsigned* gen = &g_gb[dir].gen;

    for (int t = 0; t < S_; t++) {
        const float* hrow = hbase + (t & 1)*(B_*H_);
        for (int idx = tid; idx < B_*H_; idx += 256)
            hs[(idx >> 9)*HP_ + (idx & 511)] = hrow[idx];
        __syncthreads();

        float ar, az, an;
        dot3_512(hs + b*HP_, Wr, Wz, Wn, ar, az, an);
        const float* GI = GIb + ((size_t)(b*S_ + t))*H3_;
        float r = sigf(GI[j]       + ar + br);
        float z = sigf(GI[H_+j]    + az + bz);
        float n = tanhf(GI[2*H_+j] + r*(an + bn));
        float hold = hs[b*HP_ + j];
        float hnew = (1.f - z)*n + z*hold;
        bool valid = t < L;
        hbase[((t+1) & 1)*(B_*H_) + b*H_ + j] = valid ? hnew : hold;
        float o = valid ? hnew : 0.f;
        if (dir == 0) g_enc_out[((size_t)(b*S_+t))*H2_ + j] = o;
        else          g_out_bR [((size_t)(b*S_+t))*H_  + j] = o;
        gbar2(cnt, gen, (unsigned)(t + 1), 32u);
    }
}

__global__ void k_outbw(const int* __restrict__ len)
{
    int i = blockIdx.x*blockDim.x + threadIdx.x;
    if (i >= B_*S_*H_) return;
    int j = i % H_, s = (i / H_) % S_, b = i / (H_*S_);
    int L = len[b];
    int r = (s < L) ? (L-1-s) : s;
    g_enc_out[((size_t)(b*S_+s))*H2_ + H_ + j] = g_out_bR[((size_t)(b*S_+r))*H_ + j];
}

__global__ void k_bridge(const float* __restrict__ bridge_W, const float* __restrict__ bridge_b)
{
    const int tid = threadIdx.x;
    const int b = tid & 15, j = blockIdx.x * 16 + (tid >> 4);
    const float* Wrow = bridge_W + (size_t)j*H2_;
    const float* hf = g_hf + b*H_;
    const float* hb = g_hb + b*H_;
    float acc = 0.f;
    #pragma unroll 4
    for (int k = 0; k < H_; k += 4) {
        float4 h = *(const float4*)(hf + k);
        float4 w = *(const float4*)(Wrow + k);
        acc = fmaf(h.x,w.x, fmaf(h.y,w.y, fmaf(h.z,w.z, fmaf(h.w,w.w, acc))));
    }
    #pragma unroll 4
    for (int k = 0; k < H_; k += 4) {
        float4 h = *(const float4*)(hb + k);
        float4 w = *(const float4*)(Wrow + H_ + k);
        acc = fmaf(h.x,w.x, fmaf(h.y,w.y, fmaf(h.z,w.z, fmaf(h.w,w.w, acc))));
    }
    g_hdec[b*H_ + j] = tanhf(acc + bridge_b[j]);
}

// ---------------- persistent decoder: 512 threads, 3 fast grid barriers per step ----------------
__global__ __launch_bounds__(512)
void k_dec(const float* __restrict__ Wa_dec, const float* __restrict__ Wv,
           const int* __restrict__ src, const float* __restrict__ Whd,
           const float* __restrict__ bhd)
{
    __shared__ float hs[16*HP_];
    __shared__ float esm[S_], asmx[S_];
    const int blk = blockIdx.x, tid = threadIdx.x;
    const int lane = tid & 31, w = tid >> 5;
    const int gw = blk*16 + w;
    const int j = gw >> 1;
    const int b8 = ((gw & 1) << 3) + (lane >> 2);
    const int kq = lane & 3;
    const int bq_b = blk >> 2, bq_q = blk & 3;
    unsigned* cnt = &g_gb[2].cnt;
    unsigned* gen = &g_gb[2].gen;
    unsigned era = 0;

    const int c0 = bq_q*640 + tid;
    const bool h1 = tid < 128;
    const int c1 = bq_q*640 + 512 + tid;
    const float *p0base, *p1base = 0; int st0, st1 = 0;
    int d0kind, d0off, d1kind = 0, d1off = 0;
    if (c0 < H2_) { p0base = g_enc_out + (size_t)bq_b*S_*H2_ + c0; st0 = H2_; d0kind = 0; d0off = c0; }
    else { int cc = c0 - H2_; p0base = g_encW + (size_t)bq_b*S_*H3_ + cc; st0 = H3_; d0kind = 1; d0off = cc; }
    if (h1) {
        if (c1 < H2_) { p1base = g_enc_out + (size_t)bq_b*S_*H2_ + c1; st1 = H2_; d1kind = 0; d1off = c1; }
        else { int cc = c1 - H2_; p1base = g_encW + (size_t)bq_b*S_*H3_ + cc; st1 = H3_; d1kind = 1; d1off = cc; }
    }

    for (int t = 0; t < ST_; t++) {
        const float* hrow = g_hdec + (t & 1)*(B_*H_);
        for (int idx = tid; idx < B_*H_; idx += 512)
            hs[(idx >> 9)*HP_ + (idx & 511)] = hrow[idx];
        __syncthreads();

        // P1: dp
        {
            const float* wa = Wa_dec + (size_t)j*H_ + kq*128;
            const float* x  = hs + b8*HP_ + kq*128;
            u64 a0 = 0, a1 = 0;
            #pragma unroll
            for (int k = 0; k < 128; k += 4) {
                float4 xv = *(const float4*)(x + k);
                float4 wv = *(const float4*)(wa + k);
                f2fma(a0, f2pack(xv.x, xv.y), f2pack(wv.x, wv.y));
                f2fma(a1, f2pack(xv.z, xv.w), f2pack(wv.z, wv.w));
            }
            float2 p = f2unpack(a0), q2 = f2unpack(a1);
            float s = (p.x + q2.x) + (p.y + q2.y);
            s += __shfl_xor_sync(0xffffffffu, s, 1);
            s += __shfl_xor_sync(0xffffffffu, s, 2);
            if (kq == 0) g_dps[b8*H_ + j] = s;
        }
        gbar2(cnt, gen, ++era, 64u);

        // P2: energies + softmax + ctx/gic
        {
            const float* dp = g_dps + bq_b*H_;
            #pragma unroll
            for (int i = 0; i < 8; i++) {
                int s = w*8 + i;
                const float* er = g_encP + ((size_t)(bq_b*S_ + s))*H_;
                float acc = 0.f;
                #pragma unroll
                for (int ii = 0; ii < 16; ii++) {
                    int k = lane + 32*ii;
                    acc = fmaf(tanhap(er[k] + dp[k]), Wv[k], acc);
                }
                #pragma unroll
                for (int o = 16; o; o >>= 1) acc += __shfl_xor_sync(0xffffffffu, acc, o);
                if (lane == 0)
                    esm[s] = (src[bq_b*S_ + s] != 0) ? acc : -1e9f;
            }
            __syncthreads();
            if (w == 0) {
                float v[4]; float m = -1e30f;
                #pragma unroll
                for (int i = 0; i < 4; i++) { v[i] = esm[lane + 32*i]; m = fmaxf(m, v[i]); }
                #pragma unroll
                for (int o = 16; o; o >>= 1) m = fmaxf(m, __shfl_xor_sync(0xffffffffu, m, o));
                float sum = 0.f;
                #pragma unroll
                for (int i = 0; i < 4; i++) { v[i] = expf(v[i] - m); sum += v[i]; }
                #pragma unroll
                for (int o = 16; o; o >>= 1) sum += __shfl_xor_sync(0xffffffffu, sum, o);
                float inv = 1.f / sum;
                #pragma unroll
                for (int i = 0; i < 4; i++) asmx[lane + 32*i] = v[i]*inv;
            }
            __syncthreads();
            float a0 = 0.f, a0b = 0.f, a1 = 0.f, a1b = 0.f;
            #pragma unroll 8
            for (int s = 0; s < 64; s++) {
                float wA = asmx[s], wB = asmx[s + 64];
                a0  = fmaf(wA, p0base[(size_t)s*st0], a0);
                a0b = fmaf(wB, p0base[(size_t)(s + 64)*st0], a0b);
                if (h1) {
                    a1  = fmaf(wA, p1base[(size_t)s*st1], a1);
                    a1b = fmaf(wB, p1base[(size_t)(s + 64)*st1], a1b);
                }
            }
            a0 += a0b; a1 += a1b;
            size_t n = (size_t)t*B_ + bq_b;
            float* d0 = d0kind ? (g_gict + bq_b*H3_ + d0off) : (g_feat + n*KO_ + H_ + d0off);
            *d0 = a0;
            if (h1) {
                float* d1 = d1kind ? (g_gict + bq_b*H3_ + d1off) : (g_feat + n*KO_ + H_ + d1off);
                *d1 = a1;
            }
        }
        gbar2(cnt, gen, ++era, 64u);

        // P3: GRU
        {
            const float* Wr = Whd + (size_t)j*H_ + kq*128;
            const float* Wz = Whd + (size_t)(H_+j)*H_ + kq*128;
            const float* Wn = Whd + (size_t)(2*H_+j)*H_ + kq*128;
            float ar, az, an;
            dot3_128(hs + b8*HP_ + kq*128, Wr, Wz, Wn, ar, az, an);
            ar += __shfl_xor_sync(0xffffffffu, ar, 1);
            ar += __shfl_xor_sync(0xffffffffu, ar, 2);
            az += __shfl_xor_sync(0xffffffffu, az, 1);
            az += __shfl_xor_sync(0xffffffffu, az, 2);
            an += __shfl_xor_sync(0xffffffffu, an, 1);
            an += __shfl_xor_sync(0xffffffffu, an, 2);
            if (kq == 0) {
                size_t n = (size_t)t*B_ + b8;
                const float* gie = g_GIe + n*H3_;
                const float* gic = g_gict + b8*H3_;
                float r  = sigf(gie[j]       + gic[j]       + ar + bhd[j]);
                float z  = sigf(gie[H_+j]    + gic[H_+j]    + az + bhd[H_+j]);
                float nn = tanhf(gie[2*H_+j] + gic[2*H_+j]  + r*(an + bhd[2*H_+j]));
                float hold = hs[b8*HP_ + j];
                float hnew = (1.f - z)*nn + z*hold;
                g_hdec[((t+1) & 1)*(B_*H_) + b8*H_ + j] = hnew;
                g_feat[n*KO_ + j] = hnew;
            }
        }
        gbar2(cnt, gen, ++era, 64u);
    }
}

extern "C" void kernel_launch(void* const* d_in, const int* in_sizes, int n_in,
                              void* d_out, int out_size)
{
    const int*   src      = (const int*)d_in[0];
    const int*   len      = (const int*)d_in[1];
    const int*   tgt      = (const int*)d_in[2];
    const float* enc_emb  = (const float*)d_in[3];
    const float* W_ih_f   = (const float*)d_in[4];
    const float* W_hh_f   = (const float*)d_in[5];
    const float* b_ih_f   = (const float*)d_in[6];
    const float* b_hh_f   = (const float*)d_in[7];
    const float* W_ih_b   = (const float*)d_in[8];
    const float* W_hh_b   = (const float*)d_in[9];
    const float* b_ih_b   = (const float*)d_in[10];
    const float* b_hh_b   = (const float*)d_in[11];
    const float* bridge_W = (const float*)d_in[12];
    const float* bridge_b = (const float*)d_in[13];
    const float* dec_emb  = (const float*)d_in[14];
    const float* Wa_enc   = (const float*)d_in[15];
    const float* Wa_dec   = (const float*)d_in[16];
    const float* Wv       = (const float*)d_in[17];
    const float* W_ih_d   = (const float*)d_in[18];
    const float* W_hh_d   = (const float*)d_in[19];
    const float* b_ih_d   = (const float*)d_in[20];
    const float* b_hh_d   = (const float*)d_in[21];
    const float* out_W    = (const float*)d_in[22];
    const float* out_b    = (const float*)d_in[23];
    float* out = (float*)d_out;

    float *p_emb, *p_emb_rev, *p_emb_in, *p_GI_f, *p_GI_b, *p_GIe, *p_enc_out, *p_encP, *p_encW;
    cudaGetSymbolAddress((void**)&p_emb,     g_emb);
    cudaGetSymbolAddress((void**)&p_emb_rev, g_emb_rev);
    cudaGetSymbolAddress((void**)&p_emb_in,  g_emb_in);
    cudaGetSymbolAddress((void**)&p_GI_f,    g_GI_f);
    cudaGetSymbolAddress((void**)&p_GI_b,    g_GI_b);
    cudaGetSymbolAddress((void**)&p_GIe,     g_GIe);
    cudaGetSymbolAddress((void**)&p_enc_out, g_enc_out);
    cudaGetSymbolAddress((void**)&p_encP,    g_encP);
    cudaGetSymbolAddress((void**)&p_encW,    g_encW);

    k_convW<<<1024, 256>>>(out_W);
    k_gather<<<512, 256>>>(src, len, tgt, enc_emb, dec_emb);

    k_gemm<<<dim3(H3_/128, (B_*S_)/128), 256>>>(p_emb,     W_ih_f, b_ih_f, p_GI_f, B_*S_,  H3_, E_, E_);
    k_gemm<<<dim3(H3_/128, (B_*S_)/128), 256>>>(p_emb_rev, W_ih_b, b_ih_b, p_GI_b, B_*S_,  H3_, E_, E_);
    k_gemm<<<dim3(H3_/128, (ST_*B_+127)/128), 256>>>(p_emb_in, W_ih_d, b_ih_d, p_GIe, ST_*B_, H3_, E_, KD_);

    k_enc<<<64, 256>>>(W_hh_f, b_hh_f, W_hh_b, b_hh_b, len);

    k_outbw<<<(B_*S_*H_)/256, 256>>>(len);
    k_bridge<<<H_/16, 256>>>(bridge_W, bridge_b);
    k_gemm<<<dim3(H_/128, (B_*S_)/128), 256>>>(p_enc_out, Wa_enc, 0, p_encP, B_*S_, H_, H2_, H2_);
    k_gemm<<<dim3(H3_/128, (B_*S_)/128), 256>>>(p_enc_out, W_ih_d + E_, 0, p_encW, B_*S_, H3_, H2_, KD_);

    k_dec<<<64, 512>>>(Wa_dec, Wv, src, W_hh_d, b_hh_d);

    k_convA<<<1024, 256>>>();
    k_outgemm<<<dim3(MPAD_/128, V_/128), 256>>>(out, out_b);
}

// round 16
// speedup vs baseline: 1.1795x; 1.0576x over previous
#include <cuda_runtime.h>
#include <cuda_bf16.h>

#define B_  16
#define S_  128
#define T_  128
#define ST_ 127
#define E_  256
#define H_  512
#define H2_ 1024
#define H3_ 1536
#define KD_ 1280
#define KO_ 1792
#define V_  32000
#define MPAD_ 2048
#define K3_ (3*KO_)
#define HP_ 516
#define NCH_ 168
#define STG_A 20480
#define STG_B 10240
#define TILE_SZ 20480
#define ENC_SMEM ((16*1536 + 16*HP_)*4)
#define DEC_SMEM ((4096 + 12288 + 16*HP_)*4)

typedef unsigned int u32;
typedef unsigned long long u64;

__device__ float g_emb    [B_*S_*E_];
__device__ float g_emb_rev[B_*S_*E_];
__device__ float g_emb_in [ST_*B_*E_];
__device__ float g_GI_f   [B_*S_*H3_];
__device__ float g_GI_b   [B_*S_*H3_];
__device__ float g_GIe    [ST_*B_*H3_];
__device__ float g_enc_out[B_*S_*H2_];
__device__ float g_out_bR [B_*S_*H_];
__device__ float g_encP   [B_*S_*H_];
__device__ float g_encW   [B_*S_*H3_];
__device__ float g_feat   [ST_*B_*KO_];
__device__ float g_hf  [2*B_*H_];
__device__ float g_hb  [2*B_*H_];
__device__ float g_hdec[2*B_*H_];
__device__ float g_dps [B_*H_];
__device__ float g_gict[B_*H3_];
__device__ __align__(16) unsigned char g_A3p[(size_t)8*NCH_*STG_A];
__device__ __align__(16) unsigned char g_B3p[(size_t)250*NCH_*STG_B];

struct GBS { unsigned cnt; unsigned p0[31]; unsigned gen; unsigned p1[31]; };
__device__ GBS g_gb[3];

__device__ __forceinline__ void gbar2(unsigned* cnt, unsigned* gen, unsigned era, unsigned nb) {
    __syncthreads();
    if (threadIdx.x == 0) {
        unsigned prev;
        asm volatile("atom.add.acq_rel.gpu.global.u32 %0, [%1], 1;"
                     : "=r"(prev) : "l"(cnt) : "memory");
        if (prev == era*nb - 1u) {
            asm volatile("st.release.gpu.global.u32 [%0], %1;" :: "l"(gen), "r"(era) : "memory");
        } else {
            unsigned g;
            do {
                asm volatile("ld.acquire.gpu.global.u32 %0, [%1];" : "=r"(g) : "l"(gen) : "memory");
            } while (g < era);
        }
    }
    __syncthreads();
}

__device__ __forceinline__ float sigf(float x) { return 1.f / (1.f + expf(-x)); }
__device__ __forceinline__ float tanhap(float x) {
    float y; asm("tanh.approx.f32 %0, %1;" : "=f"(y) : "f"(x)); return y;
}
__device__ __forceinline__ u64 f2pack(float a, float b) {
    u64 r; asm("mov.b64 %0, {%1, %2};" : "=l"(r) : "r"(__float_as_uint(a)), "r"(__float_as_uint(b)));
    return r;
}
__device__ __forceinline__ void f2fma(u64& d, u64 a, u64 b) {
    asm("fma.rn.f32x2 %0, %1, %2, %0;" : "+l"(d) : "l"(a), "l"(b));
}
__device__ __forceinline__ float2 f2unpack(u64 v) {
    unsigned lo, hi; asm("mov.b64 {%0, %1}, %2;" : "=r"(lo), "=r"(hi) : "l"(v));
    return make_float2(__uint_as_float(lo), __uint_as_float(hi));
}
__device__ __forceinline__ void dot3_512(const float* __restrict__ x,
    const float* __restrict__ r0, const float* __restrict__ r1,
    const float* __restrict__ r2, float& o0, float& o1, float& o2)
{
    u64 a0=0,a1=0,b0=0,b1=0,c0=0,c1=0;
    #pragma unroll 8
    for (int k = 0; k < H_; k += 4) {
        float4 xv = *(const float4*)(x + k);
        u64 xlo = f2pack(xv.x, xv.y), xhi = f2pack(xv.z, xv.w);
        float4 w0 = *(const float4*)(r0 + k);
        f2fma(a0, xlo, f2pack(w0.x, w0.y)); f2fma(a1, xhi, f2pack(w0.z, w0.w));
        float4 w1 = *(const float4*)(r1 + k);
        f2fma(b0, xlo, f2pack(w1.x, w1.y)); f2fma(b1, xhi, f2pack(w1.z, w1.w));
        float4 w2 = *(const float4*)(r2 + k);
        f2fma(c0, xlo, f2pack(w2.x, w2.y)); f2fma(c1, xhi, f2pack(w2.z, w2.w));
    }
    float2 p, q;
    p = f2unpack(a0); q = f2unpack(a1); o0 = (p.x + q.x) + (p.y + q.y);
    p = f2unpack(b0); q = f2unpack(b1); o1 = (p.x + q.x) + (p.y + q.y);
    p = f2unpack(c0); q = f2unpack(c1); o2 = (p.x + q.x) + (p.y + q.y);
}
__device__ __forceinline__ void dot3_128(const float* __restrict__ x,
    const float* __restrict__ r0, const float* __restrict__ r1,
    const float* __restrict__ r2, float& o0, float& o1, float& o2)
{
    u64 a0=0,a1=0,b0=0,b1=0,c0=0,c1=0;
    #pragma unroll
    for (int k = 0; k < 128; k += 4) {
        float4 xv = *(const float4*)(x + k);
        u64 xlo = f2pack(xv.x, xv.y), xhi = f2pack(xv.z, xv.w);
        float4 w0 = *(const float4*)(r0 + k);
        f2fma(a0, xlo, f2pack(w0.x, w0.y)); f2fma(a1, xhi, f2pack(w0.z, w0.w));
        float4 w1 = *(const float4*)(r1 + k);
        f2fma(b0, xlo, f2pack(w1.x, w1.y)); f2fma(b1, xhi, f2pack(w1.z, w1.w));
        float4 w2 = *(const float4*)(r2 + k);
        f2fma(c0, xlo, f2pack(w2.x, w2.y)); f2fma(c1, xhi, f2pack(w2.z, w2.w));
    }
    float2 p, q;
    p = f2unpack(a0); q = f2unpack(a1); o0 = (p.x + q.x) + (p.y + q.y);
    p = f2unpack(b0); q = f2unpack(b1); o1 = (p.x + q.x) + (p.y + q.y);
    p = f2unpack(c0); q = f2unpack(c1); o2 = (p.x + q.x) + (p.y + q.y);
}

__device__ __forceinline__ u32 s2u(const void* p) {
    u32 a; asm("{ .reg .u64 t; cvta.to.shared.u64 t, %1; cvt.u32.u64 %0, t; }" : "=r"(a) : "l"(p));
    return a;
}
__device__ __forceinline__ void ldmA4(u32 addr, u32* a) {
    asm volatile("ldmatrix.sync.aligned.m8n8.x4.shared.b16 {%0,%1,%2,%3}, [%4];"
        : "=r"(a[0]), "=r"(a[1]), "=r"(a[2]), "=r"(a[3]) : "r"(addr));
}
__device__ __forceinline__ void ldmB2(u32 addr, u32* b) {
    asm volatile("ldmatrix.sync.aligned.m8n8.x2.shared.b16 {%0,%1}, [%2];"
        : "=r"(b[0]), "=r"(b[1]) : "r"(addr));
}
__device__ __forceinline__ void mma16816(float* c, const u32* a, const u32* b) {
    asm volatile("mma.sync.aligned.m16n8k16.row.col.f32.bf16.bf16.f32 "
        "{%0,%1,%2,%3}, {%4,%5,%6,%7}, {%8,%9}, {%0,%1,%2,%3};"
        : "+f"(c[0]), "+f"(c[1]), "+f"(c[2]), "+f"(c[3])
        : "r"(a[0]), "r"(a[1]), "r"(a[2]), "r"(a[3]), "r"(b[0]), "r"(b[1]));
}

#define MB_INIT(mb, c)   asm volatile("mbarrier.init.shared.b64 [%0], %1;" :: "r"((u32)(mb)), "r"((u32)(c)) : "memory")
#define MB_EXPECT_TX(mb, n) asm volatile("mbarrier.arrive.expect_tx.shared.b64 _, [%0], %1;" :: "r"((u32)(mb)), "r"((u32)(n)) : "memory")
#define BULK_G2S(dst, src, n, mb) \
    asm volatile("cp.async.bulk.shared::cluster.global.mbarrier::complete_tx::bytes [%0], [%1], %2, [%3];" \
        :: "r"((u32)(dst)), "l"(src), "r"((u32)(n)), "r"((u32)(mb)) : "memory")
#define MB_WAIT(mbar, par) do { \
    u32 _m = (u32)(mbar); u32 _p = (u32)(par); u32 _d; \
    asm volatile("{\n\t.reg .pred p;\n\t" \
        "mbarrier.try_wait.parity.acquire.cta.shared::cta.b64 p, [%1], %2;\n\t" \
        "selp.b32 %0, 1, 0, p;\n\t}" : "=r"(_d) : "r"(_m), "r"(_p) : "memory"); \
    if (!_d) { \
        asm volatile("{\n\t.reg .pred P1;\n\t" \
            "WL_%=:\n\t" \
            "mbarrier.try_wait.parity.acquire.cta.shared::cta.b64 P1, [%0], %1, 0x989680;\n\t" \
            "@P1 bra.uni WD_%=;\n\tbra.uni WL_%=;\n\tWD_%=:\n\t}" \
            :: "r"(_m), "r"(_p) : "memory"); \
    } } while (0)

// ---------------- gathers + init ----------------
__global__ void k_gather(const int* __restrict__ src, const int* __restrict__ len,
                         const int* __restrict__ tgt,
                         const float* __restrict__ enc_emb, const float* __restrict__ dec_emb)
{
    if (blockIdx.x == 0 && threadIdx.x == 0) {
        #pragma unroll
        for (int i = 0; i < 3; i++) { g_gb[i].cnt = 0u; g_gb[i].gen = 0u; }
        __threadfence();
    }
    const int total = B_*S_*E_;
    for (int i = blockIdx.x*blockDim.x + threadIdx.x; i < total; i += gridDim.x*blockDim.x) {
        int e = i % E_, s = (i / E_) % S_, b = i / (E_*S_);
        int L = len[b];
        g_emb[i] = enc_emb[(size_t)src[b*S_+s]*E_ + e];
        int r = (s < L) ? (L-1-s) : s;
        g_emb_rev[i] = enc_emb[(size_t)src[b*S_+r]*E_ + e];
        if (s < ST_) {
            float v = dec_emb[(size_t)tgt[b*T_+s]*E_ + e];
            size_t n = (size_t)s*B_ + b;
            g_emb_in[n*E_ + e] = v;
            g_feat[n*KO_ + (H_+H2_) + e] = v;
        }
        if (i < 2*B_*H_) { g_hf[i] = 0.f; g_hb[i] = 0.f; }
    }
}

// ---------------- packed bf16 hi/lo conversions ----------------
__device__ __forceinline__ u32 pack_bf2(float a0, float a1) {
    __nv_bfloat16 h0 = __float2bfloat16(a0), h1 = __float2bfloat16(a1);
    return (u32)__bfloat16_as_ushort(h0) | ((u32)__bfloat16_as_ushort(h1) << 16);
}
__device__ __forceinline__ u32 pack_bf2lo(float a0, float a1) {
    __nv_bfloat16 h0 = __float2bfloat16(a0), h1 = __float2bfloat16(a1);
    float l0 = a0 - __bfloat162float(h0), l1 = a1 - __bfloat162float(h1);
    return (u32)__bfloat16_as_ushort(__float2bfloat16(l0))
         | ((u32)__bfloat16_as_ushort(__float2bfloat16(l1)) << 16);
}
__global__ void k_convW(const float* __restrict__ W)
{
    const int NKG = KO_/8;
    const size_t total = (size_t)V_*NKG;
    for (size_t i = (size_t)blockIdx.x*blockDim.x + threadIdx.x; i < total;
         i += (size_t)gridDim.x*blockDim.x) {
        int n = (int)(i / NKG), k = (int)(i % NKG) * 8;
        const float* wp = W + (size_t)n*KO_ + k;
        float4 v0 = *(const float4*)(wp), v1 = *(const float4*)(wp + 4);
        uint4 hi, lo;
        hi.x = pack_bf2(v0.x, v0.y); hi.y = pack_bf2(v0.z, v0.w);
        hi.z = pack_bf2(v1.x, v1.y); hi.w = pack_bf2(v1.z, v1.w);
        lo.x = pack_bf2lo(v0.x, v0.y); lo.y = pack_bf2lo(v0.z, v0.w);
        lo.z = pack_bf2lo(v1.x, v1.y); lo.w = pack_bf2lo(v1.z, v1.w);
        int nb = n >> 7, r = n & 127;
        #pragma unroll
        for (int t3 = 0; t3 < 3; t3++) {
            int k3 = t3*KO_ + k;
            size_t off = (((size_t)nb*NCH_ + (k3 >> 5))*128 + r)*80 + (k3 & 31)*2;
            *(uint4*)(g_B3p + off) = (t3 == 1) ? lo : hi;
        }
    }
}
__global__ void k_convA()
{
    const int NKG = KO_/8;
    const size_t total = (size_t)MPAD_*NKG;
    for (size_t i = (size_t)blockIdx.x*blockDim.x + threadIdx.x; i < total;
         i += (size_t)gridDim.x*blockDim.x) {
        int m = (int)(i / NKG), k = (int)(i % NKG) * 8;
        float4 v0 = make_float4(0.f,0.f,0.f,0.f), v1 = v0;
        if (m < ST_*B_) {
            const float* ap = g_feat + (size_t)m*KO_ + k;
            v0 = *(const float4*)(ap); v1 = *(const float4*)(ap + 4);
        }
        uint4 hi, lo;
        hi.x = pack_bf2(v0.x, v0.y); hi.y = pack_bf2(v0.z, v0.w);
        hi.z = pack_bf2(v1.x, v1.y); hi.w = pack_bf2(v1.z, v1.w);
        lo.x = pack_bf2lo(v0.x, v0.y); lo.y = pack_bf2lo(v0.z, v0.w);
        lo.z = pack_bf2lo(v1.x, v1.y); lo.w = pack_bf2lo(v1.z, v1.w);
        int mb = m >> 8, r = m & 255;
        #pragma unroll
        for (int t3 = 0; t3 < 3; t3++) {
            int k3 = t3*KO_ + k;
            size_t off = (((size_t)mb*NCH_ + (k3 >> 5))*256 + r)*80 + (k3 & 31)*2;
            *(uint4*)(g_A3p + off) = (t3 == 2) ? lo : hi;
        }
    }
}

// ---------------- HMMA output GEMM: 128x128 tile, 2 CTAs/SM, bulk 3-stage ----------------
__global__ __launch_bounds__(256, 2)
void k_outgemm(float* __restrict__ out, const float* __restrict__ bias)
{
    __shared__ __align__(16) char sm[3*TILE_SZ];
    __shared__ __align__(8) u64 mbar[3];
    const int tid = threadIdx.x, wid = tid >> 5, lane = tid & 31;
    const int wm = wid >> 2, wn = wid & 3;
    const int bx = blockIdx.x, by = blockIdx.y;
    const int m0 = bx * 128, n0 = by * 128;

    if (tid < 3) MB_INIT(s2u(&mbar[tid]), 1);
    __syncthreads();

    float acc[4][4][4];
    #pragma unroll
    for (int i = 0; i < 4; i++)
        #pragma unroll
        for (int j = 0; j < 4; j++)
            #pragma unroll
            for (int q = 0; q < 4; q++) acc[i][j][q] = 0.f;

    auto issue = [&](int c) {
        int slot = c % 3;
        u32 mb = s2u(&mbar[slot]);
        MB_EXPECT_TX(mb, TILE_SZ);
        u32 da = s2u(sm + slot*TILE_SZ);
        const unsigned char* ga = g_A3p + ((size_t)(bx >> 1)*NCH_ + c)*STG_A + (size_t)(bx & 1)*10240;
        const unsigned char* gb = g_B3p + ((size_t)by*NCH_ + c)*STG_B;
        BULK_G2S(da, ga, 10240, mb);
        BULK_G2S(da + 10240, gb, 10240, mb);
    };
    if (tid == 0) { issue(0); issue(1); }

    const int NC = NCH_;
    for (int c = 0; c < NC; c++) {
        MB_WAIT(s2u(&mbar[c % 3]), (c/3) & 1);
        if (tid == 0 && c + 2 < NC) issue(c + 2);
        char* base = sm + (c % 3)*TILE_SZ;
        const u32 aB = s2u(base), bB = s2u(base + 10240);
        #pragma unroll
        for (int ks = 0; ks < 2; ks++) {
            u32 af[4][4], bf[4][2];
            #pragma unroll
            for (int fm = 0; fm < 4; fm++)
                ldmA4(aB + (u32)((wm*64 + fm*16 + (lane & 15))*80 + ks*32 + (lane >> 4)*16), af[fm]);
            #pragma unroll
            for (int fn = 0; fn < 4; fn++)
                ldmB2(bB + (u32)((wn*32 + fn*8 + (lane & 7))*80 + ks*32 + ((lane >> 3) & 1)*16), bf[fn]);
            #pragma unroll
            for (int fm = 0; fm < 4; fm++)
                #pragma unroll
                for (int fn = 0; fn < 4; fn++)
                    mma16816(acc[fm][fn], af[fm], bf[fn]);
        }
        __syncthreads();
    }

    #pragma unroll
    for (int fm = 0; fm < 4; fm++) {
        #pragma unroll
        for (int half = 0; half < 2; half++) {
            int m = m0 + wm*64 + fm*16 + (lane >> 2) + half*8;
            if (m >= ST_*B_) continue;
            float* orow = out + ((size_t)((m & 15)*ST_ + (m >> 4)))*V_;
            #pragma unroll
            for (int fn = 0; fn < 4; fn++) {
                int nc = n0 + wn*32 + fn*8 + (lane & 3)*2;
                float2 v;
                v.x = acc[fm][fn][half*2 + 0] + bias[nc];
                v.y = acc[fm][fn][half*2 + 1] + bias[nc + 1];
                *(float2*)(orow + nc) = v;
            }
        }
    }
}

// ---------------- SIMT f32 GEMM for the small matmuls ----------------
__global__ __launch_bounds__(256, 2)
void k_gemm(const float* __restrict__ A, const float* __restrict__ W,
            const float* __restrict__ bias, float* __restrict__ C,
            int M, int N, int K, int ldw)
{
    __shared__ float As[16][132];
    __shared__ float Bs[16][132];
    const int tid = threadIdx.x;
    const int tx = tid & 15, ty = tid >> 4;
    const int m0 = blockIdx.y * 128, n0 = blockIdx.x * 128;
    const int lr = tid >> 2, lc = (tid & 3) * 4;

    u64 acc[8][4];
    #pragma unroll
    for (int i = 0; i < 8; i++)
        #pragma unroll
        for (int j = 0; j < 4; j++) acc[i][j] = 0ULL;

    for (int k0 = 0; k0 < K; k0 += 16) {
        #pragma unroll
        for (int h = 0; h < 2; h++) {
            int m = m0 + lr + h*64;
            float4 v = (m < M) ? *(const float4*)(A + (size_t)m*K + k0 + lc)
                               : make_float4(0.f,0.f,0.f,0.f);
            As[lc+0][lr+h*64] = v.x; As[lc+1][lr+h*64] = v.y;
            As[lc+2][lr+h*64] = v.z; As[lc+3][lr+h*64] = v.w;
        }
        #pragma unroll
        for (int h = 0; h < 2; h++) {
            int n = n0 + lr + h*64;
            float4 v = *(const float4*)(W + (size_t)n*ldw + k0 + lc);
            Bs[lc+0][lr+h*64] = v.x; Bs[lc+1][lr+h*64] = v.y;
            Bs[lc+2][lr+h*64] = v.z; Bs[lc+3][lr+h*64] = v.w;
        }
        __syncthreads();
        #pragma unroll
        for (int k = 0; k < 16; k++) {
            float4 a0 = *(const float4*)&As[k][ty*8];
            float4 a1 = *(const float4*)&As[k][ty*8+4];
            float4 b0 = *(const float4*)&Bs[k][tx*8];
            float4 b1 = *(const float4*)&Bs[k][tx*8+4];
            float ra[8] = {a0.x,a0.y,a0.z,a0.w,a1.x,a1.y,a1.z,a1.w};
            u64 bp[4];
            bp[0] = f2pack(b0.x, b0.y); bp[1] = f2pack(b0.z, b0.w);
            bp[2] = f2pack(b1.x, b1.y); bp[3] = f2pack(b1.z, b1.w);
            #pragma unroll
            for (int i = 0; i < 8; i++) {
                u64 ap = f2pack(ra[i], ra[i]);
                f2fma(acc[i][0], ap, bp[0]); f2fma(acc[i][1], ap, bp[1]);
                f2fma(acc[i][2], ap, bp[2]); f2fma(acc[i][3], ap, bp[3]);
            }
        }
        __syncthreads();
    }
    #pragma unroll
    for (int i = 0; i < 8; i++) {
        int m = m0 + ty*8 + i;
        if (m >= M) continue;
        float* crow = C + (size_t)m*N;
        int nc = n0 + tx*8;
        #pragma unroll
        for (int j = 0; j < 4; j++) {
            float2 v = f2unpack(acc[i][j]);
            float c0 = v.x, c1 = v.y;
            if (bias) { c0 += bias[nc+2*j]; c1 += bias[nc+2*j+1]; }
            crow[nc+2*j] = c0; crow[nc+2*j+1] = c1;
        }
    }
}

// ---------------- persistent encoder: weights preloaded in smem ----------------
__global__ __launch_bounds__(256)
void k_enc(const float* __restrict__ Wf, const float* __restrict__ bf,
           const float* __restrict__ Wb, const float* __restrict__ bb,
           const int* __restrict__ len)
{
    extern __shared__ float esm_dyn[];
    float* ws = esm_dyn;              // 16 j x 3 gates x 512
    float* hs = esm_dyn + 16*1536;    // 16 b x HP_
    const int blk = blockIdx.x;
    const int dir = blk >> 5, jb = blk & 31;
    const int tid = threadIdx.x;
    const int b = tid & 15;
    const int jj = tid >> 4;
    const float* Whh = dir ? Wb : Wf;
    const float* bhh = dir ? bb : bf;
    float* hbase = dir ? g_hb : g_hf;
    const float* GIb = dir ? g_GI_b : g_GI_f;
    const int L = len[b];
    const int j = jb*16 + jj;
    const float br = bhh[j], bz = bhh[H_+j], bn = bhh[2*H_+j];
    unsigned* cnt = &g_gb[dir].cnt;
    unsigned* gen = &g_gb[dir].gen;

    // preload weight slice: ws[(jj*3+g)*512 + k] = Whh[(g*H + jb*16+jj)*H + k]
    for (int idx = tid; idx < 16*1536; idx += 256) {
        int jl = idx / 1536, rem = idx - jl*1536;
        int g = rem >> 9, k = rem & 511;
        ws[idx] = Whh[((size_t)g*H_ + jb*16 + jl)*H_ + k];
    }

    const float* Wr = ws + jj*1536;
    const float* Wz = Wr + 512;
    const float* Wn = Wz + 512;

    for (int t = 0; t < S_; t++) {
        const float* hrow = hbase + (t & 1)*(B_*H_);
        for (int idx = tid; idx < B_*H_; idx += 256)
            hs[(idx >> 9)*HP_ + (idx & 511)] = hrow[idx];
        __syncthreads();

        float ar, az, an;
        dot3_512(hs + b*HP_, Wr, Wz, Wn, ar, az, an);
        const float* GI = GIb + ((size_t)(b*S_ + t))*H3_;
        float r = sigf(GI[j]       + ar + br);
        float z = sigf(GI[H_+j]    + az + bz);
        float n = tanhf(GI[2*H_+j] + r*(an + bn));
        float hold = hs[b*HP_ + j];
        float hnew = (1.f - z)*n + z*hold;
        bool valid = t < L;
        hbase[((t+1) & 1)*(B_*H_) + b*H_ + j] = valid ? hnew : hold;
        float o = valid ? hnew : 0.f;
        if (dir == 0) g_enc_out[((size_t)(b*S_+t))*H2_ + j] = o;
        else          g_out_bR [((size_t)(b*S_+t))*H_  + j] = o;
        gbar2(cnt, gen, (unsigned)(t + 1), 32u);
    }
}

__global__ void k_outbw(const int* __restrict__ len)
{
    int i = blockIdx.x*blockDim.x + threadIdx.x;
    if (i >= B_*S_*H_) return;
    int j = i % H_, s = (i / H_) % S_, b = i / (H_*S_);
    int L = len[b];
    int r = (s < L) ? (L-1-s) : s;
    g_enc_out[((size_t)(b*S_+s))*H2_ + H_ + j] = g_out_bR[((size_t)(b*S_+r))*H_ + j];
}

__global__ void k_bridge(const float* __restrict__ bridge_W, const float* __restrict__ bridge_b)
{
    const int tid = threadIdx.x;
    const int b = tid & 15, j = blockIdx.x * 16 + (tid >> 4);
    const float* Wrow = bridge_W + (size_t)j*H2_;
    const float* hf = g_hf + b*H_;
    const float* hb = g_hb + b*H_;
    float acc = 0.f;
    #pragma unroll 4
    for (int k = 0; k < H_; k += 4) {
        float4 h = *(const float4*)(hf + k);
        float4 w = *(const float4*)(Wrow + k);
        acc = fmaf(h.x,w.x, fmaf(h.y,w.y, fmaf(h.z,w.z, fmaf(h.w,w.w, acc))));
    }
    #pragma unroll 4
    for (int k = 0; k < H_; k += 4) {
        float4 h = *(const float4*)(hb + k);
        float4 w = *(const float4*)(Wrow + H_ + k);
        acc = fmaf(h.x,w.x, fmaf(h.y,w.y, fmaf(h.z,w.z, fmaf(h.w,w.w, acc))));
    }
    g_hdec[b*H_ + j] = tanhf(acc + bridge_b[j]);
}

// ---------------- persistent decoder: smem weights, 3 fast grid barriers/step ----------------
__global__ __launch_bounds__(512)
void k_dec(const float* __restrict__ Wa_dec, const float* __restrict__ Wv,
           const int* __restrict__ src, const float* __restrict__ Whd,
           const float* __restrict__ bhd)
{
    extern __shared__ float dsm[];
    float* wa_s  = dsm;               // 8 j x 512
    float* whd_s = dsm + 4096;        // 8 j x 3 gates x 512
    float* hs    = dsm + 4096 + 12288; // 16 b x HP_
    __shared__ float esm[S_], asmx[S_];
    const int blk = blockIdx.x, tid = threadIdx.x;
    const int lane = tid & 31, w = tid >> 5;
    const int gw = blk*16 + w;
    const int j = gw >> 1;
    const int jl = j - blk*8;
    const int b8 = ((gw & 1) << 3) + (lane >> 2);
    const int kq = lane & 3;
    const int bq_b = blk >> 2, bq_q = blk & 3;
    unsigned* cnt = &g_gb[2].cnt;
    unsigned* gen = &g_gb[2].gen;
    unsigned era = 0;

    // preload weight slices
    for (int idx = tid; idx < 4096; idx += 512)
        wa_s[idx] = Wa_dec[((size_t)(blk*8 + (idx >> 9)))*H_ + (idx & 511)];
    for (int idx = tid; idx < 12288; idx += 512) {
        int jr = idx / 1536, rem = idx - jr*1536;
        int g = rem >> 9, k = rem & 511;
        whd_s[idx] = Whd[((size_t)g*H_ + blk*8 + jr)*H_ + k];
    }

    const int c0 = bq_q*640 + tid;
    const bool h1 = tid < 128;
    const int c1 = bq_q*640 + 512 + tid;
    const float *p0base, *p1base = 0; int st0, st1 = 0;
    int d0kind, d0off, d1kind = 0, d1off = 0;
    if (c0 < H2_) { p0base = g_enc_out + (size_t)bq_b*S_*H2_ + c0; st0 = H2_; d0kind = 0; d0off = c0; }
    else { int cc = c0 - H2_; p0base = g_encW + (size_t)bq_b*S_*H3_ + cc; st0 = H3_; d0kind = 1; d0off = cc; }
    if (h1) {
        if (c1 < H2_) { p1base = g_enc_out + (size_t)bq_b*S_*H2_ + c1; st1 = H2_; d1kind = 0; d1off = c1; }
        else { int cc = c1 - H2_; p1base = g_encW + (size_t)bq_b*S_*H3_ + cc; st1 = H3_; d1kind = 1; d1off = cc; }
    }

    for (int t = 0; t < ST_; t++) {
        const float* hrow = g_hdec + (t & 1)*(B_*H_);
        for (int idx = tid; idx < B_*H_; idx += 512)
            hs[(idx >> 9)*HP_ + (idx & 511)] = hrow[idx];
        __syncthreads();

        // P1: dp
        {
            const float* wa = wa_s + jl*512 + kq*128;
            const float* x  = hs + b8*HP_ + kq*128;
            u64 a0 = 0, a1 = 0;
            #pragma unroll
            for (int k = 0; k < 128; k += 4) {
                float4 xv = *(const float4*)(x + k);
                float4 wv = *(const float4*)(wa + k);
                f2fma(a0, f2pack(xv.x, xv.y), f2pack(wv.x, wv.y));
                f2fma(a1, f2pack(xv.z, xv.w), f2pack(wv.z, wv.w));
            }
            float2 p = f2unpack(a0), q2 = f2unpack(a1);
            float s = (p.x + q2.x) + (p.y + q2.y);
            s += __shfl_xor_sync(0xffffffffu, s, 1);
            s += __shfl_xor_sync(0xffffffffu, s, 2);
            if (kq == 0) g_dps[b8*H_ + j] = s;
        }
        gbar2(cnt, gen, ++era, 64u);

        // P2: energies + softmax + ctx/gic
        {
            const float* dp = g_dps + bq_b*H_;
            #pragma unroll
            for (int i = 0; i < 8; i++) {
                int s = w*8 + i;
                const float* er = g_encP + ((size_t)(bq_b*S_ + s))*H_;
                float acc = 0.f;
                #pragma unroll
                for (int ii = 0; ii < 16; ii++) {
                    int k = lane + 32*ii;
                    acc = fmaf(tanhap(er[k] + dp[k]), Wv[k], acc);
                }
                #pragma unroll
                for (int o = 16; o; o >>= 1) acc += __shfl_xor_sync(0xffffffffu, acc, o);
                if (lane == 0)
                    esm[s] = (src[bq_b*S_ + s] != 0) ? acc : -1e9f;
            }
            __syncthreads();
            if (w == 0) {
                float v[4]; float m = -1e30f;
                #pragma unroll
                for (int i = 0; i < 4; i++) { v[i] = esm[lane + 32*i]; m = fmaxf(m, v[i]); }
                #pragma unroll
                for (int o = 16; o; o >>= 1) m = fmaxf(m, __shfl_xor_sync(0xffffffffu, m, o));
                float sum = 0.f;
                #pragma unroll
                for (int i = 0; i < 4; i++) { v[i] = expf(v[i] - m); sum += v[i]; }
                #pragma unroll
                for (int o = 16; o; o >>= 1) sum += __shfl_xor_sync(0xffffffffu, sum, o);
                float inv = 1.f / sum;
                #pragma unroll
                for (int i = 0; i < 4; i++) asmx[lane + 32*i] = v[i]*inv;
            }
            __syncthreads();
            float a0 = 0.f, a0b = 0.f, a1 = 0.f, a1b = 0.f;
            #pragma unroll 8
            for (int s = 0; s < 64; s++) {
                float wA = asmx[s], wB = asmx[s + 64];
                a0  = fmaf(wA, p0base[(size_t)s*st0], a0);
                a0b = fmaf(wB, p0base[(size_t)(s + 64)*st0], a0b);
                if (h1) {
                    a1  = fmaf(wA, p1base[(size_t)s*st1], a1);
                    a1b = fmaf(wB, p1base[(size_t)(s + 64)*st1], a1b);
                }
            }
            a0 += a0b; a1 += a1b;
            size_t n = (size_t)t*B_ + bq_b;
            float* d0 = d0kind ? (g_gict + bq_b*H3_ + d0off) : (g_feat + n*KO_ + H_ + d0off);
            *d0 = a0;
            if (h1) {
                float* d1 = d1kind ? (g_gict + bq_b*H3_ + d1off) : (g_feat + n*KO_ + H_ + d1off);
                *d1 = a1;
            }
        }
        gbar2(cnt, gen, ++era, 64u);

        // P3: GRU
        {
            const float* Wr = whd_s + jl*1536 + kq*128;
            const float* Wz = Wr + 512;
            const float* Wn = Wz + 512;
            float ar, az, an;
            dot3_128(hs + b8*HP_ + kq*128, Wr, Wz, Wn, ar, az, an);
            ar += __shfl_xor_sync(0xffffffffu, ar, 1);
            ar += __shfl_xor_sync(0xffffffffu, ar, 2);
            az += __shfl_xor_sync(0xffffffffu, az, 1);
            az += __shfl_xor_sync(0xffffffffu, az, 2);
            an += __shfl_xor_sync(0xffffffffu, an, 1);
            an += __shfl_xor_sync(0xffffffffu, an, 2);
            if (kq == 0) {
                size_t n = (size_t)t*B_ + b8;
                const float* gie = g_GIe + n*H3_;
                const float* gic = g_gict + b8*H3_;
                float r  = sigf(gie[j]       + gic[j]       + ar + bhd[j]);
                float z  = sigf(gie[H_+j]    + gic[H_+j]    + az + bhd[H_+j]);
                float nn = tanhf(gie[2*H_+j] + gic[2*H_+j]  + r*(an + bhd[2*H_+j]));
                float hold = hs[b8*HP_ + j];
                float hnew = (1.f - z)*nn + z*hold;
                g_hdec[((t+1) & 1)*(B_*H_) + b8*H_ + j] = hnew;
                g_feat[n*KO_ + j] = hnew;
            }
        }
        gbar2(cnt, gen, ++era, 64u);
    }
}

extern "C" void kernel_launch(void* const* d_in, const int* in_sizes, int n_in,
                              void* d_out, int out_size)
{
    const int*   src      = (const int*)d_in[0];
    const int*   len      = (const int*)d_in[1];
    const int*   tgt      = (const int*)d_in[2];
    const float* enc_emb  = (const float*)d_in[3];
    const float* W_ih_f   = (const float*)d_in[4];
    const float* W_hh_f   = (const float*)d_in[5];
    const float* b_ih_f   = (const float*)d_in[6];
    const float* b_hh_f   = (const float*)d_in[7];
    const float* W_ih_b   = (const float*)d_in[8];
    const float* W_hh_b   = (const float*)d_in[9];
    const float* b_ih_b   = (const float*)d_in[10];
    const float* b_hh_b   = (const float*)d_in[11];
    const float* bridge_W = (const float*)d_in[12];
    const float* bridge_b = (const float*)d_in[13];
    const float* dec_emb  = (const float*)d_in[14];
    const float* Wa_enc   = (const float*)d_in[15];
    const float* Wa_dec   = (const float*)d_in[16];
    const float* Wv       = (const float*)d_in[17];
    const float* W_ih_d   = (const float*)d_in[18];
    const float* W_hh_d   = (const float*)d_in[19];
    const float* b_ih_d   = (const float*)d_in[20];
    const float* b_hh_d   = (const float*)d_in[21];
    const float* out_W    = (const float*)d_in[22];
    const float* out_b    = (const float*)d_in[23];
    float* out = (float*)d_out;

    float *p_emb, *p_emb_rev, *p_emb_in, *p_GI_f, *p_GI_b, *p_GIe, *p_enc_out, *p_encP, *p_encW;
    cudaGetSymbolAddress((void**)&p_emb,     g_emb);
    cudaGetSymbolAddress((void**)&p_emb_rev, g_emb_rev);
    cudaGetSymbolAddress((void**)&p_emb_in,  g_emb_in);
    cudaGetSymbolAddress((void**)&p_GI_f,    g_GI_f);
    cudaGetSymbolAddress((void**)&p_GI_b,    g_GI_b);
    cudaGetSymbolAddress((void**)&p_GIe,     g_GIe);
    cudaGetSymbolAddress((void**)&p_enc_out, g_enc_out);
    cudaGetSymbolAddress((void**)&p_encP,    g_encP);
    cudaGetSymbolAddress((void**)&p_encW,    g_encW);

    cudaFuncSetAttribute(k_enc, cudaFuncAttributeMaxDynamicSharedMemorySize, ENC_SMEM);
    cudaFuncSetAttribute(k_dec, cudaFuncAttributeMaxDynamicSharedMemorySize, DEC_SMEM);

    k_convW<<<1024, 256>>>(out_W);
    k_gather<<<512, 256>>>(src, len, tgt, enc_emb, dec_emb);

    k_gemm<<<dim3(H3_/128, (B_*S_)/128), 256>>>(p_emb,     W_ih_f, b_ih_f, p_GI_f, B_*S_,  H3_, E_, E_);
    k_gemm<<<dim3(H3_/128, (B_*S_)/128), 256>>>(p_emb_rev, W_ih_b, b_ih_b, p_GI_b, B_*S_,  H3_, E_, E_);
    k_gemm<<<dim3(H3_/128, (ST_*B_+127)/128), 256>>>(p_emb_in, W_ih_d, b_ih_d, p_GIe, ST_*B_, H3_, E_, KD_);

    k_enc<<<64, 256, ENC_SMEM>>>(W_hh_f, b_hh_f, W_hh_b, b_hh_b, len);

    k_outbw<<<(B_*S_*H_)/256, 256>>>(len);
    k_bridge<<<H_/16, 256>>>(bridge_W, bridge_b);
    k_gemm<<<dim3(H_/128, (B_*S_)/128), 256>>>(p_enc_out, Wa_enc, 0, p_encP, B_*S_, H_, H2_, H2_);
    k_gemm<<<dim3(H3_/128, (B_*S_)/128), 256>>>(p_enc_out, W_ih_d + E_, 0, p_encW, B_*S_, H3_, H2_, KD_);

    k_dec<<<64, 512, DEC_SMEM>>>(Wa_dec, Wv, src, W_hh_d, b_hh_d);

    k_convA<<<1024, 256>>>();
    k_outgemm<<<dim3(MPAD_/128, V_/128), 256>>>(out, out_b);
}